// round 1
// baseline (speedup 1.0000x reference)
#include <cuda_runtime.h>
#include <math.h>

#define BB 2
#define TT 1024
#define DD 1024
#define HH 16
#define CH 64
#define BHN (BB*HH)

// ---------------- device scratch (no runtime allocation allowed) ----------------
__device__ float g_logA[BHN*TT];          // pre-cumsum logA, [bh][t]
__device__ float g_cum [BHN*TT];          // inclusive cumsum,  [bh][t]
__device__ float g_X   [BHN*TT*CH];       // silu(X),   [bh][t][c]
__device__ float g_Bm  [BHN*TT*CH];       // silu(B),   [bh][t][n]
__device__ float g_Cm  [BHN*TT*CH];       // silu(C),   [bh][t][n]
__device__ float g_gate[BHN*TT*CH];       // gate,      [bh][t][c]
__device__ float g_Yg  [BB*TT*DD];        // gated Y,   [b][t][d]

// =================================================================================
// Kernel 1: fused per-head projections.
// For each head h: out[m][o] = sum_c x[m][h*64+c] * Wcat[o][c]
// o = 0 -> logA ; 1..192 -> XBC (silu) ; 193..256 -> gate
// Tile 64(m) x 64(o), K=64 one-shot. 128 threads, 8x4 fragments.
// =================================================================================
__global__ __launch_bounds__(128) void proj_kernel(
    const float* __restrict__ inp,
    const float* __restrict__ W_logA, const float* __restrict__ b_logA,
    const float* __restrict__ W_XBC,  const float* __restrict__ b_XBC,
    const float* __restrict__ W_gate, const float* __restrict__ b_gate)
{
    __shared__ float As[64*68];
    __shared__ float Ws[64*68];

    const int h     = blockIdx.z;
    const int mbase = blockIdx.x * 64;   // over B*T (2048)
    const int obase = blockIdx.y * 64;   // 0,64,128,192,256
    const int tid   = threadIdx.x;

    // load x tile (64 rows x 64 c), float4
    for (int l4 = tid; l4 < 64*16; l4 += 128) {
        int r = l4 >> 4, c4 = l4 & 15;
        float4 v = *(const float4*)&inp[(size_t)(mbase + r) * DD + h*CH + c4*4];
        *(float4*)&As[r*68 + c4*4] = v;
    }
    // load weight tile rows obase..obase+63 from the three weight tensors
    for (int l4 = tid; l4 < 64*16; l4 += 128) {
        int r = l4 >> 4, c4 = l4 & 15;
        int o = obase + r;
        float4 v = make_float4(0.f, 0.f, 0.f, 0.f);
        if (o == 0)        v = *(const float4*)&W_logA[h*CH + c4*4];
        else if (o <= 192) v = *(const float4*)&W_XBC[((h*192) + (o-1))*CH + c4*4];
        else if (o < 257)  v = *(const float4*)&W_gate[((h*CH) + (o-193))*CH + c4*4];
        *(float4*)&Ws[r*68 + c4*4] = v;
    }
    __syncthreads();

    const int ty = tid >> 4, tx = tid & 15;
    float acc[8][4];
#pragma unroll
    for (int i = 0; i < 8; ++i)
#pragma unroll
        for (int j = 0; j < 4; ++j) acc[i][j] = 0.f;

#pragma unroll
    for (int k4 = 0; k4 < 16; ++k4) {
        float4 a[8], b[4];
#pragma unroll
        for (int i = 0; i < 8; ++i) a[i] = *(float4*)&As[(ty + 8*i)*68 + k4*4];
#pragma unroll
        for (int j = 0; j < 4; ++j) b[j] = *(float4*)&Ws[(tx + 16*j)*68 + k4*4];
#pragma unroll
        for (int i = 0; i < 8; ++i)
#pragma unroll
            for (int j = 0; j < 4; ++j) {
                acc[i][j] += a[i].x*b[j].x;
                acc[i][j] += a[i].y*b[j].y;
                acc[i][j] += a[i].z*b[j].z;
                acc[i][j] += a[i].w*b[j].w;
            }
    }

#pragma unroll
    for (int i = 0; i < 8; ++i) {
#pragma unroll
        for (int j = 0; j < 4; ++j) {
            int o = obase + tx + 16*j;
            if (o >= 257) continue;
            int m  = mbase + ty + 8*i;
            int b_ = m >> 10;           // / TT
            int t  = m & (TT-1);
            int bh = b_*HH + h;
            float v = acc[i][j];
            if (o == 0) {
                g_logA[bh*TT + t] = v + b_logA[h];
            } else if (o <= 192) {
                int oo = o - 1;
                float z = v + b_XBC[h*192 + oo];
                float s = z / (1.f + __expf(-z));     // silu
                if (oo < 64)       g_X [(bh*TT + t)*CH + oo      ] = s;
                else if (oo < 128) g_Bm[(bh*TT + t)*CH + (oo-64) ] = s;
                else               g_Cm[(bh*TT + t)*CH + (oo-128)] = s;
            } else {
                int oo = o - 193;
                g_gate[(bh*TT + t)*CH + oo] = v + b_gate[h*CH + oo];
            }
        }
    }
}

// =================================================================================
// Kernel 2: inclusive cumsum of logA over T, per (b,h). 32 blocks x 256 threads.
// =================================================================================
__global__ __launch_bounds__(256) void scan_kernel()
{
    __shared__ float s_tot[256];
    const int bh  = blockIdx.x;
    const int tid = threadIdx.x;
    const float* in = g_logA + bh*TT;

    float v0 = in[tid*4+0], v1 = in[tid*4+1], v2 = in[tid*4+2], v3 = in[tid*4+3];
    float r0 = v0, r1 = r0+v1, r2 = r1+v2, r3 = r2+v3;
    float total = r3;
    s_tot[tid] = r3;

    for (int off = 1; off < 256; off <<= 1) {
        __syncthreads();
        float add = (tid >= off) ? s_tot[tid - off] : 0.f;
        __syncthreads();
        s_tot[tid] += add;
    }
    __syncthreads();
    float excl = s_tot[tid] - total;

    float* out = g_cum + bh*TT;
    out[tid*4+0] = excl + r0;
    out[tid*4+1] = excl + r1;
    out[tid*4+2] = excl + r2;
    out[tid*4+3] = excl + r3;
}

// =================================================================================
// Kernel 3: decay attention with gating.
//   S[i][j] = (C_i . B_j) * exp(cum_i - cum_j)   (causal)
//   Y[i][:] = sum_j S[i][j] * X[j][:]            then  Y *= gate
// Per block: (bh, i-tile of 64). j-tiles limited to a 9-tile window (decay makes
// gap>=513 contributions < ~1e-7 relative; tolerance is 1e-3).
// 128 threads, 8x4 frags. Smem: C tile, B/S tile (reused), X^T tile, cums.
// =================================================================================
#define ATT_SMEM_FLOATS (3*64*68 + 128)
__global__ __launch_bounds__(128) void attn_kernel()
{
    extern __shared__ float sm[];
    float* Cs   = sm;               // [64][68]   C rows (i-tile), k-major
    float* BSs  = Cs  + 64*68;      // [64][68]   B rows (j-tile), then decayed S
    float* Xt   = BSs + 64*68;      // [64][68]   X transposed: [c][jj]
    float* cums = Xt  + 64*68;      // [0..63]=cum_i, [64..127]=cum_j

    const int it  = (int)(gridDim.x - 1) - (int)blockIdx.x;  // big tiles launch first
    const int bh  = blockIdx.y;
    const int tid = threadIdx.x;
    const int ty  = tid >> 4, tx = tid & 15;

    // load C tile (once)
    {
        const float* Cg = g_Cm + ((size_t)bh*TT + it*64)*CH;
        for (int l4 = tid; l4 < 64*16; l4 += 128) {
            int r = l4 >> 4, c4 = l4 & 15;
            *(float4*)&Cs[r*68 + c4*4] = *(const float4*)&Cg[r*CH + c4*4];
        }
        if (tid < 64) cums[tid] = g_cum[bh*TT + it*64 + tid];
    }

    float accY[8][4];
#pragma unroll
    for (int i = 0; i < 8; ++i)
#pragma unroll
        for (int j = 0; j < 4; ++j) accY[i][j] = 0.f;

    const int jt0 = (it > 8) ? (it - 8) : 0;
    for (int jt = jt0; jt <= it; ++jt) {
        __syncthreads();   // prior iteration done reading BSs/Xt
        {
            const float* Bg = g_Bm + ((size_t)bh*TT + jt*64)*CH;
            const float* Xg = g_X  + ((size_t)bh*TT + jt*64)*CH;
            for (int l4 = tid; l4 < 64*16; l4 += 128) {
                int r = l4 >> 4, c4 = l4 & 15;
                *(float4*)&BSs[r*68 + c4*4] = *(const float4*)&Bg[r*CH + c4*4];
                float4 xv = *(const float4*)&Xg[r*CH + c4*4];
                Xt[(c4*4+0)*68 + r] = xv.x;
                Xt[(c4*4+1)*68 + r] = xv.y;
                Xt[(c4*4+2)*68 + r] = xv.z;
                Xt[(c4*4+3)*68 + r] = xv.w;
            }
            if (tid < 64) cums[64 + tid] = g_cum[bh*TT + jt*64 + tid];
        }
        __syncthreads();

        // ---- S = C . B^T ----
        float accS[8][4];
#pragma unroll
        for (int i = 0; i < 8; ++i)
#pragma unroll
            for (int j = 0; j < 4; ++j) accS[i][j] = 0.f;

#pragma unroll
        for (int k4 = 0; k4 < 16; ++k4) {
            float4 a[8], b[4];
#pragma unroll
            for (int i = 0; i < 8; ++i) a[i] = *(float4*)&Cs [(ty + 8*i)*68 + k4*4];
#pragma unroll
            for (int j = 0; j < 4; ++j) b[j] = *(float4*)&BSs[(tx + 16*j)*68 + k4*4];
#pragma unroll
            for (int i = 0; i < 8; ++i)
#pragma unroll
                for (int j = 0; j < 4; ++j) {
                    accS[i][j] += a[i].x*b[j].x;
                    accS[i][j] += a[i].y*b[j].y;
                    accS[i][j] += a[i].z*b[j].z;
                    accS[i][j] += a[i].w*b[j].w;
                }
        }
        __syncthreads();   // everyone done reading B from BSs

        // ---- decay + causal mask, write S over BSs ----
        const bool diag = (jt == it);
#pragma unroll
        for (int i = 0; i < 8; ++i) {
#pragma unroll
            for (int j = 0; j < 4; ++j) {
                int ii = ty + 8*i, jj = tx + 16*j;
                float s;
                if (diag && jj > ii) s = 0.f;
                else                 s = accS[i][j] * __expf(cums[ii] - cums[64 + jj]);
                BSs[ii*68 + jj] = s;
            }
        }
        __syncthreads();

        // ---- Y += S @ X  (X transposed in smem) ----
#pragma unroll
        for (int q4 = 0; q4 < 16; ++q4) {
            float4 sf[8], xf[4];
#pragma unroll
            for (int i = 0; i < 8; ++i) sf[i] = *(float4*)&BSs[(ty + 8*i)*68 + q4*4];
#pragma unroll
            for (int j = 0; j < 4; ++j) xf[j] = *(float4*)&Xt [(tx + 16*j)*68 + q4*4];
#pragma unroll
            for (int i = 0; i < 8; ++i)
#pragma unroll
                for (int j = 0; j < 4; ++j) {
                    accY[i][j] += sf[i].x*xf[j].x;
                    accY[i][j] += sf[i].y*xf[j].y;
                    accY[i][j] += sf[i].z*xf[j].z;
                    accY[i][j] += sf[i].w*xf[j].w;
                }
        }
    }

    // ---- gate + store ----
    const int b_ = bh >> 4, h = bh & 15;
#pragma unroll
    for (int i = 0; i < 8; ++i) {
#pragma unroll
        for (int j = 0; j < 4; ++j) {
            int ii = ty + 8*i;
            int gi = it*64 + ii;
            int cc = tx + 16*j;
            float g = g_gate[((size_t)bh*TT + gi)*CH + cc];
            g_Yg[((size_t)b_*TT + gi)*DD + h*CH + cc] = accY[i][j] * g;
        }
    }
}

// =================================================================================
// Kernel 4: out = Yg @ W_out^T + b_out.  M=2048, N=1024, K=1024.
// 64x64 tiles, K chunks of 32, 128 threads, 8x4 frags.
// =================================================================================
__global__ __launch_bounds__(128) void out_gemm(
    const float* __restrict__ W_out, const float* __restrict__ b_out,
    float* __restrict__ out)
{
    __shared__ float As[64*36];
    __shared__ float Bs[64*36];

    const int mbase = blockIdx.x * 64;
    const int nbase = blockIdx.y * 64;
    const int tid   = threadIdx.x;
    const int ty    = tid >> 4, tx = tid & 15;

    float acc[8][4];
#pragma unroll
    for (int i = 0; i < 8; ++i)
#pragma unroll
        for (int j = 0; j < 4; ++j) acc[i][j] = 0.f;

    for (int kc = 0; kc < DD; kc += 32) {
        __syncthreads();
        for (int l4 = tid; l4 < 64*8; l4 += 128) {
            int r = l4 >> 3, c4 = l4 & 7;
            *(float4*)&As[r*36 + c4*4] = *(const float4*)&g_Yg [(size_t)(mbase + r)*DD + kc + c4*4];
            *(float4*)&Bs[r*36 + c4*4] = *(const float4*)&W_out[(size_t)(nbase + r)*DD + kc + c4*4];
        }
        __syncthreads();

#pragma unroll
        for (int k4 = 0; k4 < 8; ++k4) {
            float4 a[8], b[4];
#pragma unroll
            for (int i = 0; i < 8; ++i) a[i] = *(float4*)&As[(ty + 8*i)*36 + k4*4];
#pragma unroll
            for (int j = 0; j < 4; ++j) b[j] = *(float4*)&Bs[(tx + 16*j)*36 + k4*4];
#pragma unroll
            for (int i = 0; i < 8; ++i)
#pragma unroll
                for (int j = 0; j < 4; ++j) {
                    acc[i][j] += a[i].x*b[j].x;
                    acc[i][j] += a[i].y*b[j].y;
                    acc[i][j] += a[i].z*b[j].z;
                    acc[i][j] += a[i].w*b[j].w;
                }
        }
    }

#pragma unroll
    for (int i = 0; i < 8; ++i) {
#pragma unroll
        for (int j = 0; j < 4; ++j) {
            int m = mbase + ty + 8*i;
            int n = nbase + tx + 16*j;
            out[(size_t)m*DD + n] = acc[i][j] + b_out[n];
        }
    }
}

// =================================================================================
extern "C" void kernel_launch(void* const* d_in, const int* in_sizes, int n_in,
                              void* d_out, int out_size)
{
    const float* inp    = (const float*)d_in[0];
    const float* W_logA = (const float*)d_in[1];
    const float* b_logA = (const float*)d_in[2];
    const float* W_XBC  = (const float*)d_in[3];
    const float* b_XBC  = (const float*)d_in[4];
    const float* W_gate = (const float*)d_in[5];
    const float* b_gate = (const float*)d_in[6];
    const float* W_out  = (const float*)d_in[7];
    const float* b_out  = (const float*)d_in[8];
    float* out = (float*)d_out;

    proj_kernel<<<dim3(32, 5, 16), 128>>>(inp, W_logA, b_logA, W_XBC, b_XBC, W_gate, b_gate);
    scan_kernel<<<32, 256>>>();

    const int att_smem = ATT_SMEM_FLOATS * (int)sizeof(float);   // 52736 B
    cudaFuncSetAttribute(attn_kernel, cudaFuncAttributeMaxDynamicSharedMemorySize, att_smem);
    attn_kernel<<<dim3(16, 32), 128, att_smem>>>();

    out_gemm<<<dim3(32, 16), 128>>>(W_out, b_out, out);
}

// round 6
// speedup vs baseline: 1.2167x; 1.2167x over previous
#include <cuda_runtime.h>
#include <cuda_bf16.h>
#include <mma.h>
#include <math.h>
#include <cstdint>

using namespace nvcuda;

#define BB 2
#define TT 1024
#define DD 1024
#define HH 16
#define CH 64
#define BHN (BB*HH)

// ---------------- device scratch (no runtime allocation allowed) ----------------
__device__ __align__(128) float g_logA[BHN*TT];
__device__ __align__(128) float g_cum [BHN*TT];
__device__ __align__(128) float g_X   [BHN*TT*CH];
__device__ __align__(128) float g_Bm  [BHN*TT*CH];
__device__ __align__(128) float g_Cm  [BHN*TT*CH];
__device__ __align__(128) float g_gate[BHN*TT*CH];
__device__ __align__(128) float g_Yg  [BB*TT*DD];

// bf16 hi/lo decompositions for tensor-core GEMM
__device__ __align__(128) __nv_bfloat16 g_YgH[BB*TT*DD];
__device__ __align__(128) __nv_bfloat16 g_YgL[BB*TT*DD];
__device__ __align__(128) __nv_bfloat16 g_WH [DD*DD];
__device__ __align__(128) __nv_bfloat16 g_WL [DD*DD];

// ---------------- helpers ----------------
__device__ __forceinline__ uint32_t smem_u32(const void* p) {
    uint32_t a;
    asm("{ .reg .u64 t; cvta.to.shared.u64 t, %1; cvt.u32.u64 %0, t; }" : "=r"(a) : "l"(p));
    return a;
}
__device__ __forceinline__ void cp16(uint32_t dst, const void* src) {
    asm volatile("cp.async.cg.shared.global [%0], [%1], 16;" :: "r"(dst), "l"(src) : "memory");
}
#define CP_COMMIT() asm volatile("cp.async.commit_group;" ::: "memory")
#define CP_WAIT(n)  asm volatile("cp.async.wait_group %0;" :: "n"(n) : "memory")

// =================================================================================
// Kernel 1: fused per-head projections (FFMA-bound, near fp32 peak — unchanged)
// =================================================================================
__global__ __launch_bounds__(128) void proj_kernel(
    const float* __restrict__ inp,
    const float* __restrict__ W_logA, const float* __restrict__ b_logA,
    const float* __restrict__ W_XBC,  const float* __restrict__ b_XBC,
    const float* __restrict__ W_gate, const float* __restrict__ b_gate)
{
    __shared__ float As[64*68];
    __shared__ float Ws[64*68];

    const int h     = blockIdx.z;
    const int mbase = blockIdx.x * 64;
    const int obase = blockIdx.y * 64;
    const int tid   = threadIdx.x;

    for (int l4 = tid; l4 < 64*16; l4 += 128) {
        int r = l4 >> 4, c4 = l4 & 15;
        float4 v = *(const float4*)&inp[(size_t)(mbase + r) * DD + h*CH + c4*4];
        *(float4*)&As[r*68 + c4*4] = v;
    }
    for (int l4 = tid; l4 < 64*16; l4 += 128) {
        int r = l4 >> 4, c4 = l4 & 15;
        int o = obase + r;
        float4 v = make_float4(0.f, 0.f, 0.f, 0.f);
        if (o == 0)        v = *(const float4*)&W_logA[h*CH + c4*4];
        else if (o <= 192) v = *(const float4*)&W_XBC[((h*192) + (o-1))*CH + c4*4];
        else if (o < 257)  v = *(const float4*)&W_gate[((h*CH) + (o-193))*CH + c4*4];
        *(float4*)&Ws[r*68 + c4*4] = v;
    }
    __syncthreads();

    const int ty = tid >> 4, tx = tid & 15;
    float acc[8][4];
#pragma unroll
    for (int i = 0; i < 8; ++i)
#pragma unroll
        for (int j = 0; j < 4; ++j) acc[i][j] = 0.f;

#pragma unroll
    for (int k4 = 0; k4 < 16; ++k4) {
        float4 a[8], b[4];
#pragma unroll
        for (int i = 0; i < 8; ++i) a[i] = *(float4*)&As[(ty + 8*i)*68 + k4*4];
#pragma unroll
        for (int j = 0; j < 4; ++j) b[j] = *(float4*)&Ws[(tx + 16*j)*68 + k4*4];
#pragma unroll
        for (int i = 0; i < 8; ++i)
#pragma unroll
            for (int j = 0; j < 4; ++j) {
                acc[i][j] += a[i].x*b[j].x;
                acc[i][j] += a[i].y*b[j].y;
                acc[i][j] += a[i].z*b[j].z;
                acc[i][j] += a[i].w*b[j].w;
            }
    }

#pragma unroll
    for (int i = 0; i < 8; ++i) {
#pragma unroll
        for (int j = 0; j < 4; ++j) {
            int o = obase + tx + 16*j;
            if (o >= 257) continue;
            int m  = mbase + ty + 8*i;
            int b_ = m >> 10;
            int t  = m & (TT-1);
            int bh = b_*HH + h;
            float v = acc[i][j];
            if (o == 0) {
                g_logA[bh*TT + t] = v + b_logA[h];
            } else if (o <= 192) {
                int oo = o - 1;
                float z = v + b_XBC[h*192 + oo];
                float s = z / (1.f + __expf(-z));
                if (oo < 64)       g_X [(bh*TT + t)*CH + oo      ] = s;
                else if (oo < 128) g_Bm[(bh*TT + t)*CH + (oo-64) ] = s;
                else               g_Cm[(bh*TT + t)*CH + (oo-128)] = s;
            } else {
                int oo = o - 193;
                g_gate[(bh*TT + t)*CH + oo] = v + b_gate[h*CH + oo];
            }
        }
    }
}

// =================================================================================
// Kernel 2: inclusive cumsum (unchanged)
// =================================================================================
__global__ __launch_bounds__(256) void scan_kernel()
{
    __shared__ float s_tot[256];
    const int bh  = blockIdx.x;
    const int tid = threadIdx.x;
    const float* in = g_logA + bh*TT;

    float v0 = in[tid*4+0], v1 = in[tid*4+1], v2 = in[tid*4+2], v3 = in[tid*4+3];
    float r0 = v0, r1 = r0+v1, r2 = r1+v2, r3 = r2+v3;
    float total = r3;
    s_tot[tid] = r3;

    for (int off = 1; off < 256; off <<= 1) {
        __syncthreads();
        float add = (tid >= off) ? s_tot[tid - off] : 0.f;
        __syncthreads();
        s_tot[tid] += add;
    }
    __syncthreads();
    float excl = s_tot[tid] - total;

    float* out = g_cum + bh*TT;
    out[tid*4+0] = excl + r0;
    out[tid*4+1] = excl + r1;
    out[tid*4+2] = excl + r2;
    out[tid*4+3] = excl + r3;
}

// =================================================================================
// Kernel 3: decay attention with gating (unchanged)
// =================================================================================
#define ATT_SMEM_FLOATS (3*64*68 + 128)
__global__ __launch_bounds__(128) void attn_kernel()
{
    extern __shared__ float sm[];
    float* Cs   = sm;
    float* BSs  = Cs  + 64*68;
    float* Xt   = BSs + 64*68;
    float* cums = Xt  + 64*68;

    const int it  = (int)(gridDim.x - 1) - (int)blockIdx.x;
    const int bh  = blockIdx.y;
    const int tid = threadIdx.x;
    const int ty  = tid >> 4, tx = tid & 15;

    {
        const float* Cg = g_Cm + ((size_t)bh*TT + it*64)*CH;
        for (int l4 = tid; l4 < 64*16; l4 += 128) {
            int r = l4 >> 4, c4 = l4 & 15;
            *(float4*)&Cs[r*68 + c4*4] = *(const float4*)&Cg[r*CH + c4*4];
        }
        if (tid < 64) cums[tid] = g_cum[bh*TT + it*64 + tid];
    }

    float accY[8][4];
#pragma unroll
    for (int i = 0; i < 8; ++i)
#pragma unroll
        for (int j = 0; j < 4; ++j) accY[i][j] = 0.f;

    const int jt0 = (it > 8) ? (it - 8) : 0;
    for (int jt = jt0; jt <= it; ++jt) {
        __syncthreads();
        {
            const float* Bg = g_Bm + ((size_t)bh*TT + jt*64)*CH;
            const float* Xg = g_X  + ((size_t)bh*TT + jt*64)*CH;
            for (int l4 = tid; l4 < 64*16; l4 += 128) {
                int r = l4 >> 4, c4 = l4 & 15;
                *(float4*)&BSs[r*68 + c4*4] = *(const float4*)&Bg[r*CH + c4*4];
                float4 xv = *(const float4*)&Xg[r*CH + c4*4];
                Xt[(c4*4+0)*68 + r] = xv.x;
                Xt[(c4*4+1)*68 + r] = xv.y;
                Xt[(c4*4+2)*68 + r] = xv.z;
                Xt[(c4*4+3)*68 + r] = xv.w;
            }
            if (tid < 64) cums[64 + tid] = g_cum[bh*TT + jt*64 + tid];
        }
        __syncthreads();

        float accS[8][4];
#pragma unroll
        for (int i = 0; i < 8; ++i)
#pragma unroll
            for (int j = 0; j < 4; ++j) accS[i][j] = 0.f;

#pragma unroll
        for (int k4 = 0; k4 < 16; ++k4) {
            float4 a[8], b[4];
#pragma unroll
            for (int i = 0; i < 8; ++i) a[i] = *(float4*)&Cs [(ty + 8*i)*68 + k4*4];
#pragma unroll
            for (int j = 0; j < 4; ++j) b[j] = *(float4*)&BSs[(tx + 16*j)*68 + k4*4];
#pragma unroll
            for (int i = 0; i < 8; ++i)
#pragma unroll
                for (int j = 0; j < 4; ++j) {
                    accS[i][j] += a[i].x*b[j].x;
                    accS[i][j] += a[i].y*b[j].y;
                    accS[i][j] += a[i].z*b[j].z;
                    accS[i][j] += a[i].w*b[j].w;
                }
        }
        __syncthreads();

        const bool diag = (jt == it);
#pragma unroll
        for (int i = 0; i < 8; ++i) {
#pragma unroll
            for (int j = 0; j < 4; ++j) {
                int ii = ty + 8*i, jj = tx + 16*j;
                float s;
                if (diag && jj > ii) s = 0.f;
                else                 s = accS[i][j] * __expf(cums[ii] - cums[64 + jj]);
                BSs[ii*68 + jj] = s;
            }
        }
        __syncthreads();

#pragma unroll
        for (int q4 = 0; q4 < 16; ++q4) {
            float4 sf[8], xf[4];
#pragma unroll
            for (int i = 0; i < 8; ++i) sf[i] = *(float4*)&BSs[(ty + 8*i)*68 + q4*4];
#pragma unroll
            for (int j = 0; j < 4; ++j) xf[j] = *(float4*)&Xt [(tx + 16*j)*68 + q4*4];
#pragma unroll
            for (int i = 0; i < 8; ++i)
#pragma unroll
                for (int j = 0; j < 4; ++j) {
                    accY[i][j] += sf[i].x*xf[j].x;
                    accY[i][j] += sf[i].y*xf[j].y;
                    accY[i][j] += sf[i].z*xf[j].z;
                    accY[i][j] += sf[i].w*xf[j].w;
                }
        }
    }

    const int b_ = bh >> 4, h = bh & 15;
#pragma unroll
    for (int i = 0; i < 8; ++i) {
#pragma unroll
        for (int j = 0; j < 4; ++j) {
            int ii = ty + 8*i;
            int gi = it*64 + ii;
            int cc = tx + 16*j;
            float g = g_gate[((size_t)bh*TT + gi)*CH + cc];
            g_Yg[((size_t)b_*TT + gi)*DD + h*CH + cc] = accY[i][j] * g;
        }
    }
}

// =================================================================================
// Kernel 4a: fp32 -> bf16 hi/lo split for Yg (2M floats) and W_out (1M floats)
// =================================================================================
__global__ __launch_bounds__(256) void cvt_kernel(const float* __restrict__ W_out)
{
    const int i = blockIdx.x * 256 + threadIdx.x;
    const float* src;
    __nv_bfloat16 *dh, *dl;
    int base;
    if (i < 524288) { src = g_Yg;  dh = g_YgH; dl = g_YgL; base = i; }
    else            { src = W_out; dh = g_WH;  dl = g_WL;  base = i - 524288; }

    float4 v = ((const float4*)src)[base];
    float x[4] = {v.x, v.y, v.z, v.w};
    __nv_bfloat16 h[4], l[4];
#pragma unroll
    for (int k = 0; k < 4; ++k) {
        h[k] = __float2bfloat16_rn(x[k]);
        l[k] = __float2bfloat16_rn(x[k] - __bfloat162float(h[k]));
    }
    ((__nv_bfloat162*)dh)[base*2+0] = __halves2bfloat162(h[0], h[1]);
    ((__nv_bfloat162*)dh)[base*2+1] = __halves2bfloat162(h[2], h[3]);
    ((__nv_bfloat162*)dl)[base*2+0] = __halves2bfloat162(l[0], l[1]);
    ((__nv_bfloat162*)dl)[base*2+1] = __halves2bfloat162(l[2], l[3]);
}

// =================================================================================
// Kernel 4b: out = Yg @ W_out^T + b_out via nvcuda::wmma (bf16x3, fp32 acc).
// CTA 128x128, 8 warps (4m x 2n), warp tile 32x64. K-chunk 32 bf16 x 32 CHUNKS
// (R4/R5 bug: only 16 chunks -> half of K summed -> rel_err ~ 1/sqrt(2)).
// cp.async double-buffered. smem tiles: rows x 40 bf16 (80B stride, ldm=40).
// Bias folded in by pre-loading accumulators from a broadcast bias tile.
// =================================================================================
#define NCHUNK   32
#define TILE_B   10240                 // 128 rows * 80B
#define STAGE_B  (4*TILE_B)            // AH, AL, BH, BL
#define BIAS_OFF (2*STAGE_B)           // 81920
#define OG_SMEM  (BIAS_OFF + 16*128*4) // 90112

__global__ __launch_bounds__(256) void out_gemm_wmma(
    const float* __restrict__ b_out, float* __restrict__ out)
{
    extern __shared__ __align__(128) char smem[];
    const uint32_t sbase = smem_u32(smem);
    __nv_bfloat16* s_bf = (__nv_bfloat16*)smem;
    float* bias_s = (float*)(smem + BIAS_OFF);

    const int tid  = threadIdx.x;
    const int wid  = tid >> 5;
    const int warpM = wid & 3;        // 4 m-groups of 32 rows
    const int warpN = wid >> 2;       // 2 n-groups of 64 cols
    const int mb = blockIdx.x * 128;
    const int nb = blockIdx.y * 128;

    const __nv_bfloat16* __restrict__ srcs[4] = {g_YgH, g_YgL, g_WH, g_WL};

    auto issue_stage = [&](int chunk, int p) {
        const int kc = chunk * 32;
        const uint32_t sb = sbase + (uint32_t)p * STAGE_B;
#pragma unroll
        for (int s = 0; s < 8; ++s) {
            const int l = tid + s * 256;
            const int tile = l >> 9;
            const int w = l & 511;
            const int r = w >> 2;
            const int q = w & 3;
            const int grow = (tile < 2 ? mb : nb) + r;
            const __nv_bfloat16* g = srcs[tile] + (size_t)grow * DD + kc + q * 8;
            cp16(sb + tile * TILE_B + r * 80 + q * 16, g);
        }
        CP_COMMIT();
    };

    issue_stage(0, 0);

    // bias tile: 16 identical rows of this CTA's 128 output columns
    for (int i = tid; i < 16*128; i += 256) bias_s[i] = b_out[nb + (i & 127)];
    __syncthreads();

    wmma::fragment<wmma::accumulator, 16, 16, 16, float> acc[2][4];
#pragma unroll
    for (int mt = 0; mt < 2; ++mt)
#pragma unroll
        for (int nt = 0; nt < 4; ++nt)
            wmma::load_matrix_sync(acc[mt][nt], &bias_s[warpN*64 + nt*16], 128,
                                   wmma::mem_row_major);

    for (int c = 0; c < NCHUNK; ++c) {
        const int p = c & 1;
        if (c + 1 < NCHUNK) { issue_stage(c + 1, p ^ 1); CP_WAIT(1); }
        else                { CP_WAIT(0); }
        __syncthreads();

        __nv_bfloat16* sAH = s_bf + (size_t)p * (STAGE_B/2);
        __nv_bfloat16* sAL = sAH + TILE_B/2;
        __nv_bfloat16* sBH = sAH + TILE_B;
        __nv_bfloat16* sBL = sAH + 3*(TILE_B/2);

#pragma unroll
        for (int ks = 0; ks < 2; ++ks) {
            wmma::fragment<wmma::matrix_a, 16, 16, 16, __nv_bfloat16, wmma::row_major> aH[2], aL[2];
#pragma unroll
            for (int mt = 0; mt < 2; ++mt) {
                wmma::load_matrix_sync(aH[mt], &sAH[(warpM*32 + mt*16)*40 + ks*16], 40);
                wmma::load_matrix_sync(aL[mt], &sAL[(warpM*32 + mt*16)*40 + ks*16], 40);
            }
#pragma unroll
            for (int nt = 0; nt < 4; ++nt) {
                wmma::fragment<wmma::matrix_b, 16, 16, 16, __nv_bfloat16, wmma::col_major> bH, bL;
                wmma::load_matrix_sync(bH, &sBH[(warpN*64 + nt*16)*40 + ks*16], 40);
                wmma::load_matrix_sync(bL, &sBL[(warpN*64 + nt*16)*40 + ks*16], 40);
#pragma unroll
                for (int mt = 0; mt < 2; ++mt) {
                    wmma::mma_sync(acc[mt][nt], aH[mt], bH, acc[mt][nt]);
                    wmma::mma_sync(acc[mt][nt], aH[mt], bL, acc[mt][nt]);
                    wmma::mma_sync(acc[mt][nt], aL[mt], bH, acc[mt][nt]);
                }
            }
        }
        __syncthreads();
    }

    // epilogue: direct fragment stores (bias already accumulated)
#pragma unroll
    for (int mt = 0; mt < 2; ++mt)
#pragma unroll
        for (int nt = 0; nt < 4; ++nt) {
            float* dst = out + (size_t)(mb + warpM*32 + mt*16) * DD + nb + warpN*64 + nt*16;
            wmma::store_matrix_sync(dst, acc[mt][nt], DD, wmma::mem_row_major);
        }
}

// =================================================================================
extern "C" void kernel_launch(void* const* d_in, const int* in_sizes, int n_in,
                              void* d_out, int out_size)
{
    const float* inp    = (const float*)d_in[0];
    const float* W_logA = (const float*)d_in[1];
    const float* b_logA = (const float*)d_in[2];
    const float* W_XBC  = (const float*)d_in[3];
    const float* b_XBC  = (const float*)d_in[4];
    const float* W_gate = (const float*)d_in[5];
    const float* b_gate = (const float*)d_in[6];
    const float* W_out  = (const float*)d_in[7];
    const float* b_out  = (const float*)d_in[8];
    float* out = (float*)d_out;

    proj_kernel<<<dim3(32, 5, 16), 128>>>(inp, W_logA, b_logA, W_XBC, b_XBC, W_gate, b_gate);
    scan_kernel<<<32, 256>>>();

    const int att_smem = ATT_SMEM_FLOATS * (int)sizeof(float);
    cudaFuncSetAttribute(attn_kernel, cudaFuncAttributeMaxDynamicSharedMemorySize, att_smem);
    attn_kernel<<<dim3(16, 32), 128, att_smem>>>();

    cvt_kernel<<<3072, 256>>>(W_out);

    cudaFuncSetAttribute(out_gemm_wmma, cudaFuncAttributeMaxDynamicSharedMemorySize, OG_SMEM);
    out_gemm_wmma<<<dim3(16, 8), 256, OG_SMEM>>>(b_out, out);
}

// round 7
// speedup vs baseline: 1.2998x; 1.0683x over previous
#include <cuda_runtime.h>
#include <cuda_bf16.h>
#include <mma.h>
#include <math.h>
#include <cstdint>

using namespace nvcuda;

#define BB 2
#define TT 1024
#define DD 1024
#define HH 16
#define CH 64
#define BHN (BB*HH)

// ---------------- device scratch (no runtime allocation allowed) ----------------
__device__ __align__(128) float g_logA[BHN*TT];
__device__ __align__(128) float g_cum [BHN*TT];
__device__ __align__(128) float g_X   [BHN*TT*CH];
__device__ __align__(128) float g_Bm  [BHN*TT*CH];
__device__ __align__(128) float g_Cm  [BHN*TT*CH];
__device__ __align__(128) float g_gate[BHN*TT*CH];
__device__ __align__(128) float g_Yg  [BB*TT*DD];

// bf16 hi/lo decompositions for tensor-core GEMM
__device__ __align__(128) __nv_bfloat16 g_YgH[BB*TT*DD];
__device__ __align__(128) __nv_bfloat16 g_YgL[BB*TT*DD];
__device__ __align__(128) __nv_bfloat16 g_WH [DD*DD];
__device__ __align__(128) __nv_bfloat16 g_WL [DD*DD];

// ---------------- helpers ----------------
__device__ __forceinline__ uint32_t smem_u32(const void* p) {
    uint32_t a;
    asm("{ .reg .u64 t; cvta.to.shared.u64 t, %1; cvt.u32.u64 %0, t; }" : "=r"(a) : "l"(p));
    return a;
}
__device__ __forceinline__ void cp16(uint32_t dst, const void* src) {
    asm volatile("cp.async.cg.shared.global [%0], [%1], 16;" :: "r"(dst), "l"(src) : "memory");
}
#define CP_COMMIT() asm volatile("cp.async.commit_group;" ::: "memory")
#define CP_WAIT(n)  asm volatile("cp.async.wait_group %0;" :: "n"(n) : "memory")

// =================================================================================
// Kernel 1: fused per-head projections (unchanged)
// =================================================================================
__global__ __launch_bounds__(128) void proj_kernel(
    const float* __restrict__ inp,
    const float* __restrict__ W_logA, const float* __restrict__ b_logA,
    const float* __restrict__ W_XBC,  const float* __restrict__ b_XBC,
    const float* __restrict__ W_gate, const float* __restrict__ b_gate)
{
    __shared__ float As[64*68];
    __shared__ float Ws[64*68];

    const int h     = blockIdx.z;
    const int mbase = blockIdx.x * 64;
    const int obase = blockIdx.y * 64;
    const int tid   = threadIdx.x;

    for (int l4 = tid; l4 < 64*16; l4 += 128) {
        int r = l4 >> 4, c4 = l4 & 15;
        float4 v = *(const float4*)&inp[(size_t)(mbase + r) * DD + h*CH + c4*4];
        *(float4*)&As[r*68 + c4*4] = v;
    }
    for (int l4 = tid; l4 < 64*16; l4 += 128) {
        int r = l4 >> 4, c4 = l4 & 15;
        int o = obase + r;
        float4 v = make_float4(0.f, 0.f, 0.f, 0.f);
        if (o == 0)        v = *(const float4*)&W_logA[h*CH + c4*4];
        else if (o <= 192) v = *(const float4*)&W_XBC[((h*192) + (o-1))*CH + c4*4];
        else if (o < 257)  v = *(const float4*)&W_gate[((h*CH) + (o-193))*CH + c4*4];
        *(float4*)&Ws[r*68 + c4*4] = v;
    }
    __syncthreads();

    const int ty = tid >> 4, tx = tid & 15;
    float acc[8][4];
#pragma unroll
    for (int i = 0; i < 8; ++i)
#pragma unroll
        for (int j = 0; j < 4; ++j) acc[i][j] = 0.f;

#pragma unroll
    for (int k4 = 0; k4 < 16; ++k4) {
        float4 a[8], b[4];
#pragma unroll
        for (int i = 0; i < 8; ++i) a[i] = *(float4*)&As[(ty + 8*i)*68 + k4*4];
#pragma unroll
        for (int j = 0; j < 4; ++j) b[j] = *(float4*)&Ws[(tx + 16*j)*68 + k4*4];
#pragma unroll
        for (int i = 0; i < 8; ++i)
#pragma unroll
            for (int j = 0; j < 4; ++j) {
                acc[i][j] += a[i].x*b[j].x;
                acc[i][j] += a[i].y*b[j].y;
                acc[i][j] += a[i].z*b[j].z;
                acc[i][j] += a[i].w*b[j].w;
            }
    }

#pragma unroll
    for (int i = 0; i < 8; ++i) {
#pragma unroll
        for (int j = 0; j < 4; ++j) {
            int o = obase + tx + 16*j;
            if (o >= 257) continue;
            int m  = mbase + ty + 8*i;
            int b_ = m >> 10;
            int t  = m & (TT-1);
            int bh = b_*HH + h;
            float v = acc[i][j];
            if (o == 0) {
                g_logA[bh*TT + t] = v + b_logA[h];
            } else if (o <= 192) {
                int oo = o - 1;
                float z = v + b_XBC[h*192 + oo];
                float s = z / (1.f + __expf(-z));
                if (oo < 64)       g_X [(bh*TT + t)*CH + oo      ] = s;
                else if (oo < 128) g_Bm[(bh*TT + t)*CH + (oo-64) ] = s;
                else               g_Cm[(bh*TT + t)*CH + (oo-128)] = s;
            } else {
                int oo = o - 193;
                g_gate[(bh*TT + t)*CH + oo] = v + b_gate[h*CH + oo];
            }
        }
    }
}

// =================================================================================
// Kernel 2: inclusive cumsum (unchanged)
// =================================================================================
__global__ __launch_bounds__(256) void scan_kernel()
{
    __shared__ float s_tot[256];
    const int bh  = blockIdx.x;
    const int tid = threadIdx.x;
    const float* in = g_logA + bh*TT;

    float v0 = in[tid*4+0], v1 = in[tid*4+1], v2 = in[tid*4+2], v3 = in[tid*4+3];
    float r0 = v0, r1 = r0+v1, r2 = r1+v2, r3 = r2+v3;
    float total = r3;
    s_tot[tid] = r3;

    for (int off = 1; off < 256; off <<= 1) {
        __syncthreads();
        float add = (tid >= off) ? s_tot[tid - off] : 0.f;
        __syncthreads();
        s_tot[tid] += add;
    }
    __syncthreads();
    float excl = s_tot[tid] - total;

    float* out = g_cum + bh*TT;
    out[tid*4+0] = excl + r0;
    out[tid*4+1] = excl + r1;
    out[tid*4+2] = excl + r2;
    out[tid*4+3] = excl + r3;
}

// =================================================================================
// Kernel 3: decay attention via wmma bf16x3.
// Decay factorization: exp(cum_i - cum_j) = e^{cum_i-base} * e^{base-cum_j},
// base = cum[it*64]. C rows scaled by the first factor, B rows by the second
// BEFORE GEMM1 -> decay rides through the tensor cores. Only the diagonal
// j-tile needs elementwise masking.
// Per CTA: (i-tile 64, bh). 4 warps, warp w owns rows w*16..w*16+15.
// GEMM1: S = C'B'^T (3 hi/lo products); mask+hi/lo-convert S; GEMM2: Y += S X.
// smem tiles 64 x 72 bf16 (144B stride: ldmatrix 8-row phases hit banks
// 36r%32 -> conflict-free). S32 staging 64x68 fp32.
// =================================================================================
#define ATW_LDS 72
#define ATW_TILE (64*ATW_LDS*2)        // 9216 B
#define ATW_SMEM (8*ATW_TILE + 64*68*4 + 2*64*4)  // 91648

__global__ __launch_bounds__(128) void attn_wmma()
{
    extern __shared__ __align__(128) char sm[];
    __nv_bfloat16* CsH = (__nv_bfloat16*)(sm);
    __nv_bfloat16* CsL = (__nv_bfloat16*)(sm + 1*ATW_TILE);
    __nv_bfloat16* BsH = (__nv_bfloat16*)(sm + 2*ATW_TILE);
    __nv_bfloat16* BsL = (__nv_bfloat16*)(sm + 3*ATW_TILE);
    __nv_bfloat16* XsH = (__nv_bfloat16*)(sm + 4*ATW_TILE);
    __nv_bfloat16* XsL = (__nv_bfloat16*)(sm + 5*ATW_TILE);
    __nv_bfloat16* SH  = (__nv_bfloat16*)(sm + 6*ATW_TILE);
    __nv_bfloat16* SL  = (__nv_bfloat16*)(sm + 7*ATW_TILE);
    float* S32 = (float*)(sm + 8*ATW_TILE);
    float* sCi = (float*)(sm + 8*ATW_TILE + 64*68*4);
    float* sCj = sCi + 64;

    const int it  = (int)(gridDim.x - 1) - (int)blockIdx.x;
    const int bh  = blockIdx.y;
    const int tid = threadIdx.x;
    const int w   = tid >> 5;

    const float base = g_cum[bh*TT + it*64];
    if (tid < 64) sCi[tid] = __expf(g_cum[bh*TT + it*64 + tid] - base);
    __syncthreads();

    // C tile, scaled + hi/lo split (once per CTA)
    for (int idx = tid; idx < 4096; idx += 128) {
        int r = idx >> 6, c = idx & 63;
        float v = g_Cm[((size_t)bh*TT + it*64 + r)*CH + c] * sCi[r];
        __nv_bfloat16 h = __float2bfloat16_rn(v);
        CsH[r*ATW_LDS + c] = h;
        CsL[r*ATW_LDS + c] = __float2bfloat16_rn(v - __bfloat162float(h));
    }

    wmma::fragment<wmma::accumulator,16,16,16,float> yacc[4];
#pragma unroll
    for (int ct = 0; ct < 4; ++ct) wmma::fill_fragment(yacc[ct], 0.f);

    const int jt0 = (it > 8) ? (it - 8) : 0;
    for (int jt = jt0; jt <= it; ++jt) {
        __syncthreads();   // previous iteration's GEMM2 done reading Xs/SH
        if (tid < 64) sCj[tid] = __expf(base - g_cum[bh*TT + jt*64 + tid]);
        __syncthreads();

        for (int idx = tid; idx < 4096; idx += 128) {
            int r = idx >> 6, c = idx & 63;
            size_t gofs = ((size_t)bh*TT + jt*64 + r)*CH + c;
            float vb = g_Bm[gofs] * sCj[r];
            __nv_bfloat16 hb = __float2bfloat16_rn(vb);
            BsH[r*ATW_LDS + c] = hb;
            BsL[r*ATW_LDS + c] = __float2bfloat16_rn(vb - __bfloat162float(hb));
            float vx = g_X[gofs];
            __nv_bfloat16 hx = __float2bfloat16_rn(vx);
            XsH[r*ATW_LDS + c] = hx;
            XsL[r*ATW_LDS + c] = __float2bfloat16_rn(vx - __bfloat162float(hx));
        }
        __syncthreads();

        // ---- GEMM1: S = C' B'^T ----
        wmma::fragment<wmma::accumulator,16,16,16,float> sacc[4];
#pragma unroll
        for (int nt = 0; nt < 4; ++nt) wmma::fill_fragment(sacc[nt], 0.f);
#pragma unroll
        for (int k = 0; k < 4; ++k) {
            wmma::fragment<wmma::matrix_a,16,16,16,__nv_bfloat16,wmma::row_major> aH, aL;
            wmma::load_matrix_sync(aH, &CsH[(w*16)*ATW_LDS + k*16], ATW_LDS);
            wmma::load_matrix_sync(aL, &CsL[(w*16)*ATW_LDS + k*16], ATW_LDS);
#pragma unroll
            for (int nt = 0; nt < 4; ++nt) {
                wmma::fragment<wmma::matrix_b,16,16,16,__nv_bfloat16,wmma::col_major> bH, bL;
                wmma::load_matrix_sync(bH, &BsH[(nt*16)*ATW_LDS + k*16], ATW_LDS);
                wmma::load_matrix_sync(bL, &BsL[(nt*16)*ATW_LDS + k*16], ATW_LDS);
                wmma::mma_sync(sacc[nt], aH, bH, sacc[nt]);
                wmma::mma_sync(sacc[nt], aH, bL, sacc[nt]);
                wmma::mma_sync(sacc[nt], aL, bH, sacc[nt]);
            }
        }
#pragma unroll
        for (int nt = 0; nt < 4; ++nt)
            wmma::store_matrix_sync(&S32[(w*16)*68 + nt*16], sacc[nt], 68, wmma::mem_row_major);
        __syncthreads();

        // ---- mask (diag only) + hi/lo convert ----
        const bool diag = (jt == it);
        for (int idx = tid; idx < 4096; idx += 128) {
            int ii = idx >> 6, jj = idx & 63;
            float v = S32[ii*68 + jj];
            if (diag && jj > ii) v = 0.f;
            __nv_bfloat16 h = __float2bfloat16_rn(v);
            SH[ii*ATW_LDS + jj] = h;
            SL[ii*ATW_LDS + jj] = __float2bfloat16_rn(v - __bfloat162float(h));
        }
        __syncthreads();

        // ---- GEMM2: Y += S X ----
#pragma unroll
        for (int k = 0; k < 4; ++k) {
            wmma::fragment<wmma::matrix_a,16,16,16,__nv_bfloat16,wmma::row_major> aH, aL;
            wmma::load_matrix_sync(aH, &SH[(w*16)*ATW_LDS + k*16], ATW_LDS);
            wmma::load_matrix_sync(aL, &SL[(w*16)*ATW_LDS + k*16], ATW_LDS);
#pragma unroll
            for (int ct = 0; ct < 4; ++ct) {
                wmma::fragment<wmma::matrix_b,16,16,16,__nv_bfloat16,wmma::row_major> bH, bL;
                wmma::load_matrix_sync(bH, &XsH[(k*16)*ATW_LDS + ct*16], ATW_LDS);
                wmma::load_matrix_sync(bL, &XsL[(k*16)*ATW_LDS + ct*16], ATW_LDS);
                wmma::mma_sync(yacc[ct], aH, bH, yacc[ct]);
                wmma::mma_sync(yacc[ct], aH, bL, yacc[ct]);
                wmma::mma_sync(yacc[ct], aL, bH, yacc[ct]);
            }
        }
    }

    __syncthreads();
#pragma unroll
    for (int ct = 0; ct < 4; ++ct)
        wmma::store_matrix_sync(&S32[(w*16)*68 + ct*16], yacc[ct], 68, wmma::mem_row_major);
    __syncthreads();

    const int b_ = bh >> 4, h = bh & 15;
    for (int idx = tid; idx < 4096; idx += 128) {
        int ii = idx >> 6, cc = idx & 63;
        float g = g_gate[((size_t)bh*TT + it*64 + ii)*CH + cc];
        g_Yg[((size_t)b_*TT + it*64 + ii)*DD + h*CH + cc] = S32[ii*68 + cc] * g;
    }
}

// =================================================================================
// Kernel 4a: fp32 -> bf16 hi/lo split for Yg (2M floats) and W_out (1M floats)
// =================================================================================
__global__ __launch_bounds__(256) void cvt_kernel(const float* __restrict__ W_out)
{
    const int i = blockIdx.x * 256 + threadIdx.x;
    const float* src;
    __nv_bfloat16 *dh, *dl;
    int base;
    if (i < 524288) { src = g_Yg;  dh = g_YgH; dl = g_YgL; base = i; }
    else            { src = W_out; dh = g_WH;  dl = g_WL;  base = i - 524288; }

    float4 v = ((const float4*)src)[base];
    float x[4] = {v.x, v.y, v.z, v.w};
    __nv_bfloat16 h[4], l[4];
#pragma unroll
    for (int k = 0; k < 4; ++k) {
        h[k] = __float2bfloat16_rn(x[k]);
        l[k] = __float2bfloat16_rn(x[k] - __bfloat162float(h[k]));
    }
    ((__nv_bfloat162*)dh)[base*2+0] = __halves2bfloat162(h[0], h[1]);
    ((__nv_bfloat162*)dh)[base*2+1] = __halves2bfloat162(h[2], h[3]);
    ((__nv_bfloat162*)dl)[base*2+0] = __halves2bfloat162(l[0], l[1]);
    ((__nv_bfloat162*)dl)[base*2+1] = __halves2bfloat162(l[2], l[3]);
}

// =================================================================================
// Kernel 4b: out = Yg @ W_out^T + b_out via nvcuda::wmma (bf16x3, fp32 acc).
// 32 K-chunks of 32, cp.async double-buffered. (unchanged from R6)
// =================================================================================
#define NCHUNK   32
#define TILE_B   10240                 // 128 rows * 80B
#define STAGE_B  (4*TILE_B)            // AH, AL, BH, BL
#define BIAS_OFF (2*STAGE_B)           // 81920
#define OG_SMEM  (BIAS_OFF + 16*128*4) // 90112

__global__ __launch_bounds__(256) void out_gemm_wmma(
    const float* __restrict__ b_out, float* __restrict__ out)
{
    extern __shared__ __align__(128) char smem[];
    const uint32_t sbase = smem_u32(smem);
    __nv_bfloat16* s_bf = (__nv_bfloat16*)smem;
    float* bias_s = (float*)(smem + BIAS_OFF);

    const int tid  = threadIdx.x;
    const int wid  = tid >> 5;
    const int warpM = wid & 3;
    const int warpN = wid >> 2;
    const int mb = blockIdx.x * 128;
    const int nb = blockIdx.y * 128;

    const __nv_bfloat16* __restrict__ srcs[4] = {g_YgH, g_YgL, g_WH, g_WL};

    auto issue_stage = [&](int chunk, int p) {
        const int kc = chunk * 32;
        const uint32_t sb = sbase + (uint32_t)p * STAGE_B;
#pragma unroll
        for (int s = 0; s < 8; ++s) {
            const int l = tid + s * 256;
            const int tile = l >> 9;
            const int w = l & 511;
            const int r = w >> 2;
            const int q = w & 3;
            const int grow = (tile < 2 ? mb : nb) + r;
            const __nv_bfloat16* g = srcs[tile] + (size_t)grow * DD + kc + q * 8;
            cp16(sb + tile * TILE_B + r * 80 + q * 16, g);
        }
        CP_COMMIT();
    };

    issue_stage(0, 0);

    for (int i = tid; i < 16*128; i += 256) bias_s[i] = b_out[nb + (i & 127)];
    __syncthreads();

    wmma::fragment<wmma::accumulator, 16, 16, 16, float> acc[2][4];
#pragma unroll
    for (int mt = 0; mt < 2; ++mt)
#pragma unroll
        for (int nt = 0; nt < 4; ++nt)
            wmma::load_matrix_sync(acc[mt][nt], &bias_s[warpN*64 + nt*16], 128,
                                   wmma::mem_row_major);

    for (int c = 0; c < NCHUNK; ++c) {
        const int p = c & 1;
        if (c + 1 < NCHUNK) { issue_stage(c + 1, p ^ 1); CP_WAIT(1); }
        else                { CP_WAIT(0); }
        __syncthreads();

        __nv_bfloat16* sAH = s_bf + (size_t)p * (STAGE_B/2);
        __nv_bfloat16* sAL = sAH + TILE_B/2;
        __nv_bfloat16* sBH = sAH + TILE_B;
        __nv_bfloat16* sBL = sAH + 3*(TILE_B/2);

#pragma unroll
        for (int ks = 0; ks < 2; ++ks) {
            wmma::fragment<wmma::matrix_a, 16, 16, 16, __nv_bfloat16, wmma::row_major> aH[2], aL[2];
#pragma unroll
            for (int mt = 0; mt < 2; ++mt) {
                wmma::load_matrix_sync(aH[mt], &sAH[(warpM*32 + mt*16)*40 + ks*16], 40);
                wmma::load_matrix_sync(aL[mt], &sAL[(warpM*32 + mt*16)*40 + ks*16], 40);
            }
#pragma unroll
            for (int nt = 0; nt < 4; ++nt) {
                wmma::fragment<wmma::matrix_b, 16, 16, 16, __nv_bfloat16, wmma::col_major> bH, bL;
                wmma::load_matrix_sync(bH, &sBH[(warpN*64 + nt*16)*40 + ks*16], 40);
                wmma::load_matrix_sync(bL, &sBL[(warpN*64 + nt*16)*40 + ks*16], 40);
#pragma unroll
                for (int mt = 0; mt < 2; ++mt) {
                    wmma::mma_sync(acc[mt][nt], aH[mt], bH, acc[mt][nt]);
                    wmma::mma_sync(acc[mt][nt], aH[mt], bL, acc[mt][nt]);
                    wmma::mma_sync(acc[mt][nt], aL[mt], bH, acc[mt][nt]);
                }
            }
        }
        __syncthreads();
    }

#pragma unroll
    for (int mt = 0; mt < 2; ++mt)
#pragma unroll
        for (int nt = 0; nt < 4; ++nt) {
            float* dst = out + (size_t)(mb + warpM*32 + mt*16) * DD + nb + warpN*64 + nt*16;
            wmma::store_matrix_sync(dst, acc[mt][nt], DD, wmma::mem_row_major);
        }
}

// =================================================================================
extern "C" void kernel_launch(void* const* d_in, const int* in_sizes, int n_in,
                              void* d_out, int out_size)
{
    const float* inp    = (const float*)d_in[0];
    const float* W_logA = (const float*)d_in[1];
    const float* b_logA = (const float*)d_in[2];
    const float* W_XBC  = (const float*)d_in[3];
    const float* b_XBC  = (const float*)d_in[4];
    const float* W_gate = (const float*)d_in[5];
    const float* b_gate = (const float*)d_in[6];
    const float* W_out  = (const float*)d_in[7];
    const float* b_out  = (const float*)d_in[8];
    float* out = (float*)d_out;

    proj_kernel<<<dim3(32, 5, 16), 128>>>(inp, W_logA, b_logA, W_XBC, b_XBC, W_gate, b_gate);
    scan_kernel<<<32, 256>>>();

    cudaFuncSetAttribute(attn_wmma, cudaFuncAttributeMaxDynamicSharedMemorySize, ATW_SMEM);
    attn_wmma<<<dim3(16, 32), 128, ATW_SMEM>>>();

    cvt_kernel<<<3072, 256>>>(W_out);

    cudaFuncSetAttribute(out_gemm_wmma, cudaFuncAttributeMaxDynamicSharedMemorySize, OG_SMEM);
    out_gemm_wmma<<<dim3(16, 8), 256, OG_SMEM>>>(b_out, out);
}

// round 8
// speedup vs baseline: 1.5730x; 1.2102x over previous
#include <cuda_runtime.h>
#include <cuda_bf16.h>
#include <mma.h>
#include <math.h>
#include <cstdint>

using namespace nvcuda;

#define BB 2
#define TT 1024
#define DD 1024
#define HH 16
#define CH 64
#define BHN (BB*HH)

// ---------------- device scratch (no runtime allocation allowed) ----------------
__device__ __align__(128) float g_logA[BHN*TT];
__device__ __align__(128) float g_cum [BHN*TT];
__device__ __align__(128) float g_gate[BHN*TT*CH];

// bf16 hi/lo activations (written directly by proj_kernel)
__device__ __align__(128) __nv_bfloat16 g_Xh[BHN*TT*CH];
__device__ __align__(128) __nv_bfloat16 g_Xl[BHN*TT*CH];
__device__ __align__(128) __nv_bfloat16 g_Bh[BHN*TT*CH];
__device__ __align__(128) __nv_bfloat16 g_Bl[BHN*TT*CH];
__device__ __align__(128) __nv_bfloat16 g_Chh[BHN*TT*CH];
__device__ __align__(128) __nv_bfloat16 g_Cll[BHN*TT*CH];

// bf16 hi/lo for the output GEMM
__device__ __align__(128) __nv_bfloat16 g_YgH[BB*TT*DD];
__device__ __align__(128) __nv_bfloat16 g_YgL[BB*TT*DD];
__device__ __align__(128) __nv_bfloat16 g_WH [DD*DD];
__device__ __align__(128) __nv_bfloat16 g_WL [DD*DD];

// ---------------- helpers ----------------
__device__ __forceinline__ uint32_t smem_u32(const void* p) {
    uint32_t a;
    asm("{ .reg .u64 t; cvta.to.shared.u64 t, %1; cvt.u32.u64 %0, t; }" : "=r"(a) : "l"(p));
    return a;
}
__device__ __forceinline__ void cp16(uint32_t dst, const void* src) {
    asm volatile("cp.async.cg.shared.global [%0], [%1], 16;" :: "r"(dst), "l"(src) : "memory");
}
#define CP_COMMIT() asm volatile("cp.async.commit_group;" ::: "memory")
#define CP_WAIT(n)  asm volatile("cp.async.wait_group %0;" :: "n"(n) : "memory")

// =================================================================================
// Kernel 1: fused per-head projections. Emits X/B/C as bf16 hi/lo directly.
// =================================================================================
__global__ __launch_bounds__(128) void proj_kernel(
    const float* __restrict__ inp,
    const float* __restrict__ W_logA, const float* __restrict__ b_logA,
    const float* __restrict__ W_XBC,  const float* __restrict__ b_XBC,
    const float* __restrict__ W_gate, const float* __restrict__ b_gate)
{
    __shared__ float As[64*68];
    __shared__ float Ws[64*68];

    const int h     = blockIdx.z;
    const int mbase = blockIdx.x * 64;
    const int obase = blockIdx.y * 64;
    const int tid   = threadIdx.x;

    for (int l4 = tid; l4 < 64*16; l4 += 128) {
        int r = l4 >> 4, c4 = l4 & 15;
        float4 v = *(const float4*)&inp[(size_t)(mbase + r) * DD + h*CH + c4*4];
        *(float4*)&As[r*68 + c4*4] = v;
    }
    for (int l4 = tid; l4 < 64*16; l4 += 128) {
        int r = l4 >> 4, c4 = l4 & 15;
        int o = obase + r;
        float4 v = make_float4(0.f, 0.f, 0.f, 0.f);
        if (o == 0)        v = *(const float4*)&W_logA[h*CH + c4*4];
        else if (o <= 192) v = *(const float4*)&W_XBC[((h*192) + (o-1))*CH + c4*4];
        else if (o < 257)  v = *(const float4*)&W_gate[((h*CH) + (o-193))*CH + c4*4];
        *(float4*)&Ws[r*68 + c4*4] = v;
    }
    __syncthreads();

    const int ty = tid >> 4, tx = tid & 15;
    float acc[8][4];
#pragma unroll
    for (int i = 0; i < 8; ++i)
#pragma unroll
        for (int j = 0; j < 4; ++j) acc[i][j] = 0.f;

#pragma unroll
    for (int k4 = 0; k4 < 16; ++k4) {
        float4 a[8], b[4];
#pragma unroll
        for (int i = 0; i < 8; ++i) a[i] = *(float4*)&As[(ty + 8*i)*68 + k4*4];
#pragma unroll
        for (int j = 0; j < 4; ++j) b[j] = *(float4*)&Ws[(tx + 16*j)*68 + k4*4];
#pragma unroll
        for (int i = 0; i < 8; ++i)
#pragma unroll
            for (int j = 0; j < 4; ++j) {
                acc[i][j] += a[i].x*b[j].x;
                acc[i][j] += a[i].y*b[j].y;
                acc[i][j] += a[i].z*b[j].z;
                acc[i][j] += a[i].w*b[j].w;
            }
    }

#pragma unroll
    for (int i = 0; i < 8; ++i) {
#pragma unroll
        for (int j = 0; j < 4; ++j) {
            int o = obase + tx + 16*j;
            if (o >= 257) continue;
            int m  = mbase + ty + 8*i;
            int b_ = m >> 10;
            int t  = m & (TT-1);
            int bh = b_*HH + h;
            float v = acc[i][j];
            if (o == 0) {
                g_logA[bh*TT + t] = v + b_logA[h];
            } else if (o <= 192) {
                int oo = o - 1;
                float z = v + b_XBC[h*192 + oo];
                float s = z / (1.f + __expf(-z));
                __nv_bfloat16 hi = __float2bfloat16_rn(s);
                __nv_bfloat16 lo = __float2bfloat16_rn(s - __bfloat162float(hi));
                size_t idx;
                if (oo < 64)       { idx = ((size_t)bh*TT + t)*CH + oo;       g_Xh[idx]=hi; g_Xl[idx]=lo; }
                else if (oo < 128) { idx = ((size_t)bh*TT + t)*CH + (oo-64);  g_Bh[idx]=hi; g_Bl[idx]=lo; }
                else               { idx = ((size_t)bh*TT + t)*CH + (oo-128); g_Chh[idx]=hi; g_Cll[idx]=lo; }
            } else {
                int oo = o - 193;
                g_gate[((size_t)bh*TT + t)*CH + oo] = v + b_gate[h*CH + oo];
            }
        }
    }
}

// =================================================================================
// Kernel 2: inclusive cumsum (unchanged)
// =================================================================================
__global__ __launch_bounds__(256) void scan_kernel()
{
    __shared__ float s_tot[256];
    const int bh  = blockIdx.x;
    const int tid = threadIdx.x;
    const float* in = g_logA + bh*TT;

    float v0 = in[tid*4+0], v1 = in[tid*4+1], v2 = in[tid*4+2], v3 = in[tid*4+3];
    float r0 = v0, r1 = r0+v1, r2 = r1+v2, r3 = r2+v3;
    float total = r3;
    s_tot[tid] = r3;

    for (int off = 1; off < 256; off <<= 1) {
        __syncthreads();
        float add = (tid >= off) ? s_tot[tid - off] : 0.f;
        __syncthreads();
        s_tot[tid] += add;
    }
    __syncthreads();
    float excl = s_tot[tid] - total;

    float* out = g_cum + bh*TT;
    out[tid*4+0] = excl + r0;
    out[tid*4+1] = excl + r1;
    out[tid*4+2] = excl + r2;
    out[tid*4+3] = excl + r3;
}

// =================================================================================
// Kernel 3: decay attention via wmma bf16x3 — conversion-free inner loop.
// G = C B^T raw on tensor cores; decay sCi[ii]*sCj[jj] + causal mask applied in
// the single S elementwise pass; GEMM2 Y += S X. All activation tiles arrive as
// precomputed bf16 hi/lo via cp.async. 256 threads: warp w -> mrow=w&3 (16 rows),
// nh=w>>2 (2 of 4 col-tiles). Epilogue writes YgH/YgL directly (gate folded).
// smem bf16 tiles 64x72 (144B stride, conflict-free ldmatrix phases).
// =================================================================================
#define ATW_LDS  72
#define ATW_TILE (64*ATW_LDS*2)                    // 9216 B
#define ATW_SMEM (8*ATW_TILE + 64*68*4 + 2*64*4)   // 91648

__global__ __launch_bounds__(256) void attn_wmma()
{
    extern __shared__ __align__(128) char sm[];
    const uint32_t sbase = smem_u32(sm);
    __nv_bfloat16* Chs = (__nv_bfloat16*)(sm);
    __nv_bfloat16* Cls = (__nv_bfloat16*)(sm + 1*ATW_TILE);
    __nv_bfloat16* Bhs = (__nv_bfloat16*)(sm + 2*ATW_TILE);
    __nv_bfloat16* Bls = (__nv_bfloat16*)(sm + 3*ATW_TILE);
    __nv_bfloat16* Xhs = (__nv_bfloat16*)(sm + 4*ATW_TILE);
    __nv_bfloat16* Xls = (__nv_bfloat16*)(sm + 5*ATW_TILE);
    __nv_bfloat16* Shs = (__nv_bfloat16*)(sm + 6*ATW_TILE);
    __nv_bfloat16* Sls = (__nv_bfloat16*)(sm + 7*ATW_TILE);
    float* S32 = (float*)(sm + 8*ATW_TILE);
    float* sCi = (float*)(sm + 8*ATW_TILE + 64*68*4);
    float* sCj = sCi + 64;

    const int it  = 15 - (int)blockIdx.x;    // long windows launch first
    const int bh  = blockIdx.y;
    const int tid = threadIdx.x;
    const int w   = tid >> 5;
    const int mrow = w & 3;
    const int nh   = w >> 2;                 // 0..1

    const float base = g_cum[bh*TT + it*64];
    if (tid < 64) sCi[tid] = __expf(g_cum[bh*TT + it*64 + tid] - base);

    // C tiles (hi/lo), loaded once
    {
        const __nv_bfloat16* s0[2] = {g_Chh, g_Cll};
#pragma unroll
        for (int s = 0; s < 4; ++s) {
            int l = tid + s*256;
            int tile = l >> 9, ww = l & 511, r = ww >> 3, q = ww & 7;
            const __nv_bfloat16* g = s0[tile] + ((size_t)bh*TT + it*64 + r)*CH + q*8;
            cp16(sbase + (uint32_t)(tile*ATW_TILE + r*144 + q*16), g);
        }
        CP_COMMIT();
    }

    wmma::fragment<wmma::accumulator,16,16,16,float> yacc[2];
#pragma unroll
    for (int t2 = 0; t2 < 2; ++t2) wmma::fill_fragment(yacc[t2], 0.f);

    const int jt0 = (it > 8) ? (it - 8) : 0;
    for (int jt = jt0; jt <= it; ++jt) {
        __syncthreads();   // previous iteration done reading Bs/Xs/Shs
        if (tid < 64) sCj[tid] = __expf(base - g_cum[bh*TT + jt*64 + tid]);
        {
            const __nv_bfloat16* s4[4] = {g_Bh, g_Bl, g_Xh, g_Xl};
#pragma unroll
            for (int s = 0; s < 8; ++s) {
                int l = tid + s*256;
                int tile = l >> 9, ww = l & 511, r = ww >> 3, q = ww & 7;
                const __nv_bfloat16* g = s4[tile] + ((size_t)bh*TT + jt*64 + r)*CH + q*8;
                cp16(sbase + (uint32_t)((2+tile)*ATW_TILE + r*144 + q*16), g);
            }
            CP_COMMIT();
        }
        CP_WAIT(0);
        __syncthreads();

        // ---- GEMM1: G = C B^T (raw) ----
        wmma::fragment<wmma::accumulator,16,16,16,float> sacc[2];
#pragma unroll
        for (int t2 = 0; t2 < 2; ++t2) wmma::fill_fragment(sacc[t2], 0.f);
#pragma unroll
        for (int k = 0; k < 4; ++k) {
            wmma::fragment<wmma::matrix_a,16,16,16,__nv_bfloat16,wmma::row_major> aH, aL;
            wmma::load_matrix_sync(aH, &Chs[(mrow*16)*ATW_LDS + k*16], ATW_LDS);
            wmma::load_matrix_sync(aL, &Cls[(mrow*16)*ATW_LDS + k*16], ATW_LDS);
#pragma unroll
            for (int t2 = 0; t2 < 2; ++t2) {
                const int nt = nh*2 + t2;
                wmma::fragment<wmma::matrix_b,16,16,16,__nv_bfloat16,wmma::col_major> bH, bL;
                wmma::load_matrix_sync(bH, &Bhs[(nt*16)*ATW_LDS + k*16], ATW_LDS);
                wmma::load_matrix_sync(bL, &Bls[(nt*16)*ATW_LDS + k*16], ATW_LDS);
                wmma::mma_sync(sacc[t2], aH, bH, sacc[t2]);
                wmma::mma_sync(sacc[t2], aH, bL, sacc[t2]);
                wmma::mma_sync(sacc[t2], aL, bH, sacc[t2]);
            }
        }
#pragma unroll
        for (int t2 = 0; t2 < 2; ++t2)
            wmma::store_matrix_sync(&S32[(mrow*16)*68 + (nh*2+t2)*16], sacc[t2], 68,
                                    wmma::mem_row_major);
        __syncthreads();

        // ---- decay + mask + hi/lo convert (single elementwise pass) ----
        const bool diag = (jt == it);
        for (int idx = tid; idx < 4096; idx += 256) {
            int ii = idx >> 6, jj = idx & 63;
            float v = S32[ii*68 + jj] * sCi[ii] * sCj[jj];
            if (diag && jj > ii) v = 0.f;
            __nv_bfloat16 h = __float2bfloat16_rn(v);
            Shs[ii*ATW_LDS + jj] = h;
            Sls[ii*ATW_LDS + jj] = __float2bfloat16_rn(v - __bfloat162float(h));
        }
        __syncthreads();

        // ---- GEMM2: Y += S X ----
#pragma unroll
        for (int k = 0; k < 4; ++k) {
            wmma::fragment<wmma::matrix_a,16,16,16,__nv_bfloat16,wmma::row_major> aH, aL;
            wmma::load_matrix_sync(aH, &Shs[(mrow*16)*ATW_LDS + k*16], ATW_LDS);
            wmma::load_matrix_sync(aL, &Sls[(mrow*16)*ATW_LDS + k*16], ATW_LDS);
#pragma unroll
            for (int t2 = 0; t2 < 2; ++t2) {
                const int ct = nh*2 + t2;
                wmma::fragment<wmma::matrix_b,16,16,16,__nv_bfloat16,wmma::row_major> bH, bL;
                wmma::load_matrix_sync(bH, &Xhs[(k*16)*ATW_LDS + ct*16], ATW_LDS);
                wmma::load_matrix_sync(bL, &Xls[(k*16)*ATW_LDS + ct*16], ATW_LDS);
                wmma::mma_sync(yacc[t2], aH, bH, yacc[t2]);
                wmma::mma_sync(yacc[t2], aH, bL, yacc[t2]);
                wmma::mma_sync(yacc[t2], aL, bH, yacc[t2]);
            }
        }
    }

    __syncthreads();
#pragma unroll
    for (int t2 = 0; t2 < 2; ++t2)
        wmma::store_matrix_sync(&S32[(mrow*16)*68 + (nh*2+t2)*16], yacc[t2], 68,
                                wmma::mem_row_major);
    __syncthreads();

    // gate + write YgH/YgL directly (no fp32 Yg, no cvt pass)
    const int b_ = bh >> 4, h = bh & 15;
    for (int idx = tid; idx < 4096; idx += 256) {
        int ii = idx >> 6, cc = idx & 63;
        float v = S32[ii*68 + cc] * g_gate[((size_t)bh*TT + it*64 + ii)*CH + cc];
        size_t o = ((size_t)b_*TT + it*64 + ii)*DD + h*CH + cc;
        __nv_bfloat16 hh = __float2bfloat16_rn(v);
        g_YgH[o] = hh;
        g_YgL[o] = __float2bfloat16_rn(v - __bfloat162float(hh));
    }
}

// =================================================================================
// Kernel 4a: fp32 -> bf16 hi/lo split for W_out only (Yg handled in attn epilogue)
// =================================================================================
__global__ __launch_bounds__(256) void cvt_kernel(const float* __restrict__ W_out)
{
    const int i = blockIdx.x * 256 + threadIdx.x;   // < 262144 float4s
    float4 v = ((const float4*)W_out)[i];
    float x[4] = {v.x, v.y, v.z, v.w};
    __nv_bfloat16 h[4], l[4];
#pragma unroll
    for (int k = 0; k < 4; ++k) {
        h[k] = __float2bfloat16_rn(x[k]);
        l[k] = __float2bfloat16_rn(x[k] - __bfloat162float(h[k]));
    }
    ((__nv_bfloat162*)g_WH)[i*2+0] = __halves2bfloat162(h[0], h[1]);
    ((__nv_bfloat162*)g_WH)[i*2+1] = __halves2bfloat162(h[2], h[3]);
    ((__nv_bfloat162*)g_WL)[i*2+0] = __halves2bfloat162(l[0], l[1]);
    ((__nv_bfloat162*)g_WL)[i*2+1] = __halves2bfloat162(l[2], l[3]);
}

// =================================================================================
// Kernel 4b: out = Yg @ W_out^T + b_out via nvcuda::wmma (bf16x3, fp32 acc).
// 32 K-chunks of 32, cp.async double-buffered. (unchanged from R6)
// =================================================================================
#define NCHUNK   32
#define TILE_B   10240                 // 128 rows * 80B
#define STAGE_B  (4*TILE_B)            // AH, AL, BH, BL
#define BIAS_OFF (2*STAGE_B)           // 81920
#define OG_SMEM  (BIAS_OFF + 16*128*4) // 90112

__global__ __launch_bounds__(256) void out_gemm_wmma(
    const float* __restrict__ b_out, float* __restrict__ out)
{
    extern __shared__ __align__(128) char smem[];
    const uint32_t sbase = smem_u32(smem);
    __nv_bfloat16* s_bf = (__nv_bfloat16*)smem;
    float* bias_s = (float*)(smem + BIAS_OFF);

    const int tid  = threadIdx.x;
    const int wid  = tid >> 5;
    const int warpM = wid & 3;
    const int warpN = wid >> 2;
    const int mb = blockIdx.x * 128;
    const int nb = blockIdx.y * 128;

    const __nv_bfloat16* __restrict__ srcs[4] = {g_YgH, g_YgL, g_WH, g_WL};

    auto issue_stage = [&](int chunk, int p) {
        const int kc = chunk * 32;
        const uint32_t sb = sbase + (uint32_t)p * STAGE_B;
#pragma unroll
        for (int s = 0; s < 8; ++s) {
            const int l = tid + s * 256;
            const int tile = l >> 9;
            const int w = l & 511;
            const int r = w >> 2;
            const int q = w & 3;
            const int grow = (tile < 2 ? mb : nb) + r;
            const __nv_bfloat16* g = srcs[tile] + (size_t)grow * DD + kc + q * 8;
            cp16(sb + tile * TILE_B + r * 80 + q * 16, g);
        }
        CP_COMMIT();
    };

    issue_stage(0, 0);

    for (int i = tid; i < 16*128; i += 256) bias_s[i] = b_out[nb + (i & 127)];
    __syncthreads();

    wmma::fragment<wmma::accumulator, 16, 16, 16, float> acc[2][4];
#pragma unroll
    for (int mt = 0; mt < 2; ++mt)
#pragma unroll
        for (int nt = 0; nt < 4; ++nt)
            wmma::load_matrix_sync(acc[mt][nt], &bias_s[warpN*64 + nt*16], 128,
                                   wmma::mem_row_major);

    for (int c = 0; c < NCHUNK; ++c) {
        const int p = c & 1;
        if (c + 1 < NCHUNK) { issue_stage(c + 1, p ^ 1); CP_WAIT(1); }
        else                { CP_WAIT(0); }
        __syncthreads();

        __nv_bfloat16* sAH = s_bf + (size_t)p * (STAGE_B/2);
        __nv_bfloat16* sAL = sAH + TILE_B/2;
        __nv_bfloat16* sBH = sAH + TILE_B;
        __nv_bfloat16* sBL = sAH + 3*(TILE_B/2);

#pragma unroll
        for (int ks = 0; ks < 2; ++ks) {
            wmma::fragment<wmma::matrix_a, 16, 16, 16, __nv_bfloat16, wmma::row_major> aH[2], aL[2];
#pragma unroll
            for (int mt = 0; mt < 2; ++mt) {
                wmma::load_matrix_sync(aH[mt], &sAH[(warpM*32 + mt*16)*40 + ks*16], 40);
                wmma::load_matrix_sync(aL[mt], &sAL[(warpM*32 + mt*16)*40 + ks*16], 40);
            }
#pragma unroll
            for (int nt = 0; nt < 4; ++nt) {
                wmma::fragment<wmma::matrix_b, 16, 16, 16, __nv_bfloat16, wmma::col_major> bH, bL;
                wmma::load_matrix_sync(bH, &sBH[(warpN*64 + nt*16)*40 + ks*16], 40);
                wmma::load_matrix_sync(bL, &sBL[(warpN*64 + nt*16)*40 + ks*16], 40);
#pragma unroll
                for (int mt = 0; mt < 2; ++mt) {
                    wmma::mma_sync(acc[mt][nt], aH[mt], bH, acc[mt][nt]);
                    wmma::mma_sync(acc[mt][nt], aH[mt], bL, acc[mt][nt]);
                    wmma::mma_sync(acc[mt][nt], aL[mt], bH, acc[mt][nt]);
                }
            }
        }
        __syncthreads();
    }

#pragma unroll
    for (int mt = 0; mt < 2; ++mt)
#pragma unroll
        for (int nt = 0; nt < 4; ++nt) {
            float* dst = out + (size_t)(mb + warpM*32 + mt*16) * DD + nb + warpN*64 + nt*16;
            wmma::store_matrix_sync(dst, acc[mt][nt], DD, wmma::mem_row_major);
        }
}

// =================================================================================
extern "C" void kernel_launch(void* const* d_in, const int* in_sizes, int n_in,
                              void* d_out, int out_size)
{
    const float* inp    = (const float*)d_in[0];
    const float* W_logA = (const float*)d_in[1];
    const float* b_logA = (const float*)d_in[2];
    const float* W_XBC  = (const float*)d_in[3];
    const float* b_XBC  = (const float*)d_in[4];
    const float* W_gate = (const float*)d_in[5];
    const float* b_gate = (const float*)d_in[6];
    const float* W_out  = (const float*)d_in[7];
    const float* b_out  = (const float*)d_in[8];
    float* out = (float*)d_out;

    proj_kernel<<<dim3(32, 5, 16), 128>>>(inp, W_logA, b_logA, W_XBC, b_XBC, W_gate, b_gate);
    scan_kernel<<<32, 256>>>();

    cudaFuncSetAttribute(attn_wmma, cudaFuncAttributeMaxDynamicSharedMemorySize, ATW_SMEM);
    attn_wmma<<<dim3(16, 32), 256, ATW_SMEM>>>();

    cvt_kernel<<<1024, 256>>>(W_out);

    cudaFuncSetAttribute(out_gemm_wmma, cudaFuncAttributeMaxDynamicSharedMemorySize, OG_SMEM);
    out_gemm_wmma<<<dim3(16, 8), 256, OG_SMEM>>>(b_out, out);
}

// round 9
// speedup vs baseline: 1.9657x; 1.2497x over previous
#include <cuda_runtime.h>
#include <cuda_bf16.h>
#include <mma.h>
#include <math.h>
#include <cstdint>

using namespace nvcuda;

#define BB 2
#define TT 1024
#define DD 1024
#define HH 16
#define CH 64
#define BHN (BB*HH)
#define NCH 16            // chunks per sequence

// ---------------- device scratch (no runtime allocation allowed) ----------------
__device__ __align__(128) float g_logA[BHN*TT];
__device__ __align__(128) float g_cum [BHN*TT];
__device__ __align__(128) float g_gate[BHN*TT*CH];

// bf16 hi/lo activations (written directly by proj_kernel)
__device__ __align__(128) __nv_bfloat16 g_Xh[BHN*TT*CH];
__device__ __align__(128) __nv_bfloat16 g_Xl[BHN*TT*CH];
__device__ __align__(128) __nv_bfloat16 g_Bh[BHN*TT*CH];
__device__ __align__(128) __nv_bfloat16 g_Bl[BHN*TT*CH];
__device__ __align__(128) __nv_bfloat16 g_Chh[BHN*TT*CH];
__device__ __align__(128) __nv_bfloat16 g_Cll[BHN*TT*CH];

// chunked-scan intermediates
__device__ __align__(128) float         g_P  [BHN*NCH*64*64];   // chunk moments (fp32)
__device__ __align__(128) __nv_bfloat16 g_Sth[BHN*NCH*64*64];   // states hi
__device__ __align__(128) __nv_bfloat16 g_Stl[BHN*NCH*64*64];   // states lo

// bf16 hi/lo for the output GEMM
__device__ __align__(128) __nv_bfloat16 g_YgH[BB*TT*DD];
__device__ __align__(128) __nv_bfloat16 g_YgL[BB*TT*DD];
__device__ __align__(128) __nv_bfloat16 g_WH [DD*DD];
__device__ __align__(128) __nv_bfloat16 g_WL [DD*DD];

// ---------------- helpers ----------------
__device__ __forceinline__ uint32_t smem_u32(const void* p) {
    uint32_t a;
    asm("{ .reg .u64 t; cvta.to.shared.u64 t, %1; cvt.u32.u64 %0, t; }" : "=r"(a) : "l"(p));
    return a;
}
__device__ __forceinline__ void cp16(uint32_t dst, const void* src) {
    asm volatile("cp.async.cg.shared.global [%0], [%1], 16;" :: "r"(dst), "l"(src) : "memory");
}
#define CP_COMMIT() asm volatile("cp.async.commit_group;" ::: "memory")
#define CP_WAIT(n)  asm volatile("cp.async.wait_group %0;" :: "n"(n) : "memory")

// =================================================================================
// Kernel 1: fused per-head projections. Emits X/B/C as bf16 hi/lo directly.
// =================================================================================
__global__ __launch_bounds__(128) void proj_kernel(
    const float* __restrict__ inp,
    const float* __restrict__ W_logA, const float* __restrict__ b_logA,
    const float* __restrict__ W_XBC,  const float* __restrict__ b_XBC,
    const float* __restrict__ W_gate, const float* __restrict__ b_gate)
{
    __shared__ float As[64*68];
    __shared__ float Ws[64*68];

    const int h     = blockIdx.z;
    const int mbase = blockIdx.x * 64;
    const int obase = blockIdx.y * 64;
    const int tid   = threadIdx.x;

    for (int l4 = tid; l4 < 64*16; l4 += 128) {
        int r = l4 >> 4, c4 = l4 & 15;
        float4 v = *(const float4*)&inp[(size_t)(mbase + r) * DD + h*CH + c4*4];
        *(float4*)&As[r*68 + c4*4] = v;
    }
    for (int l4 = tid; l4 < 64*16; l4 += 128) {
        int r = l4 >> 4, c4 = l4 & 15;
        int o = obase + r;
        float4 v = make_float4(0.f, 0.f, 0.f, 0.f);
        if (o == 0)        v = *(const float4*)&W_logA[h*CH + c4*4];
        else if (o <= 192) v = *(const float4*)&W_XBC[((h*192) + (o-1))*CH + c4*4];
        else if (o < 257)  v = *(const float4*)&W_gate[((h*CH) + (o-193))*CH + c4*4];
        *(float4*)&Ws[r*68 + c4*4] = v;
    }
    __syncthreads();

    const int ty = tid >> 4, tx = tid & 15;
    float acc[8][4];
#pragma unroll
    for (int i = 0; i < 8; ++i)
#pragma unroll
        for (int j = 0; j < 4; ++j) acc[i][j] = 0.f;

#pragma unroll
    for (int k4 = 0; k4 < 16; ++k4) {
        float4 a[8], b[4];
#pragma unroll
        for (int i = 0; i < 8; ++i) a[i] = *(float4*)&As[(ty + 8*i)*68 + k4*4];
#pragma unroll
        for (int j = 0; j < 4; ++j) b[j] = *(float4*)&Ws[(tx + 16*j)*68 + k4*4];
#pragma unroll
        for (int i = 0; i < 8; ++i)
#pragma unroll
            for (int j = 0; j < 4; ++j) {
                acc[i][j] += a[i].x*b[j].x;
                acc[i][j] += a[i].y*b[j].y;
                acc[i][j] += a[i].z*b[j].z;
                acc[i][j] += a[i].w*b[j].w;
            }
    }

#pragma unroll
    for (int i = 0; i < 8; ++i) {
#pragma unroll
        for (int j = 0; j < 4; ++j) {
            int o = obase + tx + 16*j;
            if (o >= 257) continue;
            int m  = mbase + ty + 8*i;
            int b_ = m >> 10;
            int t  = m & (TT-1);
            int bh = b_*HH + h;
            float v = acc[i][j];
            if (o == 0) {
                g_logA[bh*TT + t] = v + b_logA[h];
            } else if (o <= 192) {
                int oo = o - 1;
                float z = v + b_XBC[h*192 + oo];
                float s = z / (1.f + __expf(-z));
                __nv_bfloat16 hi = __float2bfloat16_rn(s);
                __nv_bfloat16 lo = __float2bfloat16_rn(s - __bfloat162float(hi));
                size_t idx;
                if (oo < 64)       { idx = ((size_t)bh*TT + t)*CH + oo;       g_Xh[idx]=hi; g_Xl[idx]=lo; }
                else if (oo < 128) { idx = ((size_t)bh*TT + t)*CH + (oo-64);  g_Bh[idx]=hi; g_Bl[idx]=lo; }
                else               { idx = ((size_t)bh*TT + t)*CH + (oo-128); g_Chh[idx]=hi; g_Cll[idx]=lo; }
            } else {
                int oo = o - 193;
                g_gate[((size_t)bh*TT + t)*CH + oo] = v + b_gate[h*CH + oo];
            }
        }
    }
}

// =================================================================================
// Kernel 2: inclusive cumsum (unchanged)
// =================================================================================
__global__ __launch_bounds__(256) void scan_kernel()
{
    __shared__ float s_tot[256];
    const int bh  = blockIdx.x;
    const int tid = threadIdx.x;
    const float* in = g_logA + bh*TT;

    float v0 = in[tid*4+0], v1 = in[tid*4+1], v2 = in[tid*4+2], v3 = in[tid*4+3];
    float r0 = v0, r1 = r0+v1, r2 = r1+v2, r3 = r2+v3;
    float total = r3;
    s_tot[tid] = r3;

    for (int off = 1; off < 256; off <<= 1) {
        __syncthreads();
        float add = (tid >= off) ? s_tot[tid - off] : 0.f;
        __syncthreads();
        s_tot[tid] += add;
    }
    __syncthreads();
    float excl = s_tot[tid] - total;

    float* out = g_cum + bh*TT;
    out[tid*4+0] = excl + r0;
    out[tid*4+1] = excl + r1;
    out[tid*4+2] = excl + r2;
    out[tid*4+3] = excl + r3;
}

// =================================================================================
// Kernel 3a: chunk moments P_k = B'^T @ X,  B'_j = e^{E_k - cum_j} B_j.
// B reconstructed exactly (hi+lo), rescaled, re-split. wmma bf16x3, fp32 out.
// grid (15, 32): P_15 never used by the scan.
// =================================================================================
#define KC_LDS 72
__global__ __launch_bounds__(256) void state_kernel()
{
    __shared__ __nv_bfloat16 Bp_h[64*KC_LDS], Bp_l[64*KC_LDS];
    __shared__ __nv_bfloat16 Xh_s[64*KC_LDS], Xl_s[64*KC_LDS];
    __shared__ float sc[64];

    const int k   = blockIdx.x;
    const int bh  = blockIdx.y;
    const int tid = threadIdx.x;
    const int w = tid >> 5, mrow = w & 3, nh = w >> 2;

    // X tiles via cp.async
    const uint32_t xh_b = smem_u32(Xh_s), xl_b = smem_u32(Xl_s);
#pragma unroll
    for (int s = 0; s < 4; ++s) {
        int l = tid + s*256;
        int tile = l >> 9, ww = l & 511, r = ww >> 3, q = ww & 7;
        const __nv_bfloat16* g = (tile ? g_Xl : g_Xh) + ((size_t)bh*TT + k*64 + r)*CH + q*8;
        cp16((tile ? xl_b : xh_b) + (uint32_t)(r*144 + q*16), g);
    }
    CP_COMMIT();
    if (tid < 64)
        sc[tid] = __expf(g_cum[bh*TT + k*64 + 63] - g_cum[bh*TT + k*64 + tid]);
    __syncthreads();

    // B' = scale * (Bh + Bl), re-split to hi/lo in smem
#pragma unroll
    for (int q = 0; q < 16; ++q) {
        int idx = tid + q*256;
        int ii = idx >> 6, jj = idx & 63;
        size_t go = ((size_t)bh*TT + k*64 + ii)*CH + jj;
        float v = (__bfloat162float(g_Bh[go]) + __bfloat162float(g_Bl[go])) * sc[ii];
        __nv_bfloat16 h = __float2bfloat16_rn(v);
        Bp_h[ii*KC_LDS + jj] = h;
        Bp_l[ii*KC_LDS + jj] = __float2bfloat16_rn(v - __bfloat162float(h));
    }
    CP_WAIT(0);
    __syncthreads();

    // P[m=N][n=ch] = sum_j B'[j][m] X[j][n]  (A col_major, B row_major)
    wmma::fragment<wmma::accumulator,16,16,16,float> pacc[2];
#pragma unroll
    for (int t2 = 0; t2 < 2; ++t2) wmma::fill_fragment(pacc[t2], 0.f);
#pragma unroll
    for (int kk = 0; kk < 4; ++kk) {
        wmma::fragment<wmma::matrix_a,16,16,16,__nv_bfloat16,wmma::col_major> aH, aL;
        wmma::load_matrix_sync(aH, &Bp_h[(kk*16)*KC_LDS + mrow*16], KC_LDS);
        wmma::load_matrix_sync(aL, &Bp_l[(kk*16)*KC_LDS + mrow*16], KC_LDS);
#pragma unroll
        for (int t2 = 0; t2 < 2; ++t2) {
            const int nt = nh*2 + t2;
            wmma::fragment<wmma::matrix_b,16,16,16,__nv_bfloat16,wmma::row_major> bH, bL;
            wmma::load_matrix_sync(bH, &Xh_s[(kk*16)*KC_LDS + nt*16], KC_LDS);
            wmma::load_matrix_sync(bL, &Xl_s[(kk*16)*KC_LDS + nt*16], KC_LDS);
            wmma::mma_sync(pacc[t2], aH, bH, pacc[t2]);
            wmma::mma_sync(pacc[t2], aH, bL, pacc[t2]);
            wmma::mma_sync(pacc[t2], aL, bH, pacc[t2]);
        }
    }
#pragma unroll
    for (int t2 = 0; t2 < 2; ++t2) {
        float* dst = g_P + ((size_t)bh*NCH + k)*4096 + (mrow*16)*64 + (nh*2+t2)*16;
        wmma::store_matrix_sync(dst, pacc[t2], 64, wmma::mem_row_major);
    }
}

// =================================================================================
// Kernel 3b: sequential state scan. S^{(k+1)} = e^{E_k - E_{k-1}} S^{(k)} + P_k.
// grid (32, 8): blockIdx.y splits the 4096 elements; k-loop in registers.
// Emits per-chunk states as bf16 hi/lo.
// =================================================================================
__global__ __launch_bounds__(256) void scan_state()
{
    const int bh  = blockIdx.x;
    const int eb  = blockIdx.y * 512;
    const int tid = threadIdx.x;
    float S[2] = {0.f, 0.f};

    for (int k = 0; k < NCH; ++k) {
        size_t so = ((size_t)bh*NCH + k)*4096 + eb;
#pragma unroll
        for (int e = 0; e < 2; ++e) {
            int idx = tid + e*256;
            __nv_bfloat16 h = __float2bfloat16_rn(S[e]);
            g_Sth[so + idx] = h;
            g_Stl[so + idx] = __float2bfloat16_rn(S[e] - __bfloat162float(h));
        }
        if (k < NCH-1) {
            float Ek = g_cum[bh*TT + k*64 + 63];
            float Ep = (k > 0) ? g_cum[bh*TT + k*64 - 1] : 0.f;
            float d  = __expf(Ek - Ep);
            size_t po = ((size_t)bh*NCH + k)*4096 + eb;
#pragma unroll
            for (int e = 0; e < 2; ++e)
                S[e] = d*S[e] + g_P[po + tid + e*256];
        }
    }
}

// =================================================================================
// Kernel 3c: per-chunk output.
//   intra: G = C B^T (raw), decay sCi*sCj + causal mask -> Sintra (reuses B smem),
//          Yintra = Sintra @ X
//   inter: Z = C @ State^{(k)};  Y = Yintra + sCi * Z;  gate; emit YgH/YgL.
// 256 threads, 8 warps: warp (mrow = w&3, nh = w>>2) owns rows mrow*16 x cols nh*32
// for ALL GEMM outputs -> convert passes are warp-local (no extra syncs).
// 3 block syncs total per CTA.
// =================================================================================
#define AC_TILE (64*KC_LDS*2)                         // 9216
#define AC_S32A (8*AC_TILE)                           // 73728
#define AC_S32B (AC_S32A + 64*68*4)                   // 91136
#define AC_SCI  (AC_S32B + 64*68*4)                   // 108544
#define AC_SMEM (AC_SCI + 2*64*4)                     // 109056

__global__ __launch_bounds__(256) void attn_chunk()
{
    extern __shared__ __align__(128) char sm[];
    const uint32_t sbase = smem_u32(sm);
    __nv_bfloat16* Ch  = (__nv_bfloat16*)(sm);
    __nv_bfloat16* Cl  = (__nv_bfloat16*)(sm + 1*AC_TILE);
    __nv_bfloat16* Bh  = (__nv_bfloat16*)(sm + 2*AC_TILE);   // -> SintraH after GEMM1
    __nv_bfloat16* Bl  = (__nv_bfloat16*)(sm + 3*AC_TILE);   // -> SintraL
    __nv_bfloat16* Xh  = (__nv_bfloat16*)(sm + 4*AC_TILE);
    __nv_bfloat16* Xl  = (__nv_bfloat16*)(sm + 5*AC_TILE);
    __nv_bfloat16* Sth = (__nv_bfloat16*)(sm + 6*AC_TILE);
    __nv_bfloat16* Stl = (__nv_bfloat16*)(sm + 7*AC_TILE);
    float* S32a = (float*)(sm + AC_S32A);
    float* S32b = (float*)(sm + AC_S32B);
    float* sCi  = (float*)(sm + AC_SCI);
    float* sCj  = sCi + 64;

    const int k   = blockIdx.x;
    const int bh  = blockIdx.y;
    const int tid = threadIdx.x;
    const int w = tid >> 5, mrow = w & 3, nh = w >> 2;

    // 6 activation tiles + 2 state tiles via cp.async
    {
        const __nv_bfloat16* act[6] = {g_Chh, g_Cll, g_Bh, g_Bl, g_Xh, g_Xl};
#pragma unroll
        for (int s = 0; s < 12; ++s) {
            int l = tid + s*256;
            int tile = l >> 9, ww = l & 511, r = ww >> 3, q = ww & 7;
            const __nv_bfloat16* g = act[tile] + ((size_t)bh*TT + k*64 + r)*CH + q*8;
            cp16(sbase + (uint32_t)(tile*AC_TILE + r*144 + q*16), g);
        }
#pragma unroll
        for (int s = 0; s < 4; ++s) {
            int l = tid + s*256;
            int tile = l >> 9, ww = l & 511, r = ww >> 3, q = ww & 7;
            const __nv_bfloat16* g = (tile ? g_Stl : g_Sth) + ((size_t)bh*NCH + k)*4096 + r*64 + q*8;
            cp16(sbase + (uint32_t)((6+tile)*AC_TILE + r*144 + q*16), g);
        }
        CP_COMMIT();
    }
    {
        const float bk = (k > 0) ? g_cum[bh*TT + k*64 - 1] : 0.f;
        if (tid < 64)  sCi[tid] = __expf(g_cum[bh*TT + k*64 + tid] - bk);
        else if (tid < 128) sCj[tid-64] = __expf(bk - g_cum[bh*TT + k*64 + (tid-64)]);
    }
    CP_WAIT(0);
    __syncthreads();   // S1: tiles + sCi/sCj visible

    // ---- GEMM1: G = C B^T (raw) ----
    wmma::fragment<wmma::accumulator,16,16,16,float> sacc[2];
#pragma unroll
    for (int t2 = 0; t2 < 2; ++t2) wmma::fill_fragment(sacc[t2], 0.f);
#pragma unroll
    for (int kk = 0; kk < 4; ++kk) {
        wmma::fragment<wmma::matrix_a,16,16,16,__nv_bfloat16,wmma::row_major> aH, aL;
        wmma::load_matrix_sync(aH, &Ch[(mrow*16)*KC_LDS + kk*16], KC_LDS);
        wmma::load_matrix_sync(aL, &Cl[(mrow*16)*KC_LDS + kk*16], KC_LDS);
#pragma unroll
        for (int t2 = 0; t2 < 2; ++t2) {
            const int nt = nh*2 + t2;
            wmma::fragment<wmma::matrix_b,16,16,16,__nv_bfloat16,wmma::col_major> bH, bL;
            wmma::load_matrix_sync(bH, &Bh[(nt*16)*KC_LDS + kk*16], KC_LDS);
            wmma::load_matrix_sync(bL, &Bl[(nt*16)*KC_LDS + kk*16], KC_LDS);
            wmma::mma_sync(sacc[t2], aH, bH, sacc[t2]);
            wmma::mma_sync(sacc[t2], aH, bL, sacc[t2]);
            wmma::mma_sync(sacc[t2], aL, bH, sacc[t2]);
        }
    }
#pragma unroll
    for (int t2 = 0; t2 < 2; ++t2)
        wmma::store_matrix_sync(&S32a[(mrow*16)*68 + (nh*2+t2)*16], sacc[t2], 68,
                                wmma::mem_row_major);
    __syncthreads();   // S2: all warps done reading B tiles + S32a complete

    // ---- decay + mask + hi/lo convert (own patch) into B region ----
#pragma unroll
    for (int q = 0; q < 16; ++q) {
        int idx = (tid & 31) + q*32;           // 512 elems per warp patch
        int ii = mrow*16 + (idx >> 5);
        int jj = nh*32 + (idx & 31);
        float v = S32a[ii*68 + jj] * sCi[ii] * sCj[jj];
        if (jj > ii) v = 0.f;
        __nv_bfloat16 h = __float2bfloat16_rn(v);
        Bh[ii*KC_LDS + jj] = h;                // SintraH
        Bl[ii*KC_LDS + jj] = __float2bfloat16_rn(v - __bfloat162float(h));
    }
    __syncthreads();   // S3: Sintra visible to all warps

    // ---- GEMM2: Yintra = Sintra @ X ;  GEMM3: Z = C @ State ----
    wmma::fragment<wmma::accumulator,16,16,16,float> yacc[2], zacc[2];
#pragma unroll
    for (int t2 = 0; t2 < 2; ++t2) { wmma::fill_fragment(yacc[t2], 0.f); wmma::fill_fragment(zacc[t2], 0.f); }
#pragma unroll
    for (int kk = 0; kk < 4; ++kk) {
        wmma::fragment<wmma::matrix_a,16,16,16,__nv_bfloat16,wmma::row_major> aH, aL, cH, cL;
        wmma::load_matrix_sync(aH, &Bh[(mrow*16)*KC_LDS + kk*16], KC_LDS);   // Sintra
        wmma::load_matrix_sync(aL, &Bl[(mrow*16)*KC_LDS + kk*16], KC_LDS);
        wmma::load_matrix_sync(cH, &Ch[(mrow*16)*KC_LDS + kk*16], KC_LDS);   // C
        wmma::load_matrix_sync(cL, &Cl[(mrow*16)*KC_LDS + kk*16], KC_LDS);
#pragma unroll
        for (int t2 = 0; t2 < 2; ++t2) {
            const int ct = nh*2 + t2;
            wmma::fragment<wmma::matrix_b,16,16,16,__nv_bfloat16,wmma::row_major> bH, bL, sH, sL;
            wmma::load_matrix_sync(bH, &Xh[(kk*16)*KC_LDS + ct*16], KC_LDS);
            wmma::load_matrix_sync(bL, &Xl[(kk*16)*KC_LDS + ct*16], KC_LDS);
            wmma::mma_sync(yacc[t2], aH, bH, yacc[t2]);
            wmma::mma_sync(yacc[t2], aH, bL, yacc[t2]);
            wmma::mma_sync(yacc[t2], aL, bH, yacc[t2]);
            wmma::load_matrix_sync(sH, &Sth[(kk*16)*KC_LDS + ct*16], KC_LDS);
            wmma::load_matrix_sync(sL, &Stl[(kk*16)*KC_LDS + ct*16], KC_LDS);
            wmma::mma_sync(zacc[t2], cH, sH, zacc[t2]);
            wmma::mma_sync(zacc[t2], cH, sL, zacc[t2]);
            wmma::mma_sync(zacc[t2], cL, sH, zacc[t2]);
        }
    }
#pragma unroll
    for (int t2 = 0; t2 < 2; ++t2) {
        wmma::store_matrix_sync(&S32a[(mrow*16)*68 + (nh*2+t2)*16], yacc[t2], 68, wmma::mem_row_major);
        wmma::store_matrix_sync(&S32b[(mrow*16)*68 + (nh*2+t2)*16], zacc[t2], 68, wmma::mem_row_major);
    }
    __syncwarp();      // own patch only

    // ---- combine + gate + emit YgH/YgL (own patch) ----
    const int b_ = bh >> 4, h = bh & 15;
#pragma unroll
    for (int q = 0; q < 16; ++q) {
        int idx = (tid & 31) + q*32;
        int ii = mrow*16 + (idx >> 5);
        int cc = nh*32 + (idx & 31);
        float y = S32a[ii*68 + cc] + sCi[ii] * S32b[ii*68 + cc];
        float v = y * g_gate[((size_t)bh*TT + k*64 + ii)*CH + cc];
        size_t o = ((size_t)b_*TT + k*64 + ii)*DD + h*CH + cc;
        __nv_bfloat16 hh = __float2bfloat16_rn(v);
        g_YgH[o] = hh;
        g_YgL[o] = __float2bfloat16_rn(v - __bfloat162float(hh));
    }
}

// =================================================================================
// Kernel 4a: fp32 -> bf16 hi/lo split for W_out
// =================================================================================
__global__ __launch_bounds__(256) void cvt_kernel(const float* __restrict__ W_out)
{
    const int i = blockIdx.x * 256 + threadIdx.x;
    float4 v = ((const float4*)W_out)[i];
    float x[4] = {v.x, v.y, v.z, v.w};
    __nv_bfloat16 h[4], l[4];
#pragma unroll
    for (int k = 0; k < 4; ++k) {
        h[k] = __float2bfloat16_rn(x[k]);
        l[k] = __float2bfloat16_rn(x[k] - __bfloat162float(h[k]));
    }
    ((__nv_bfloat162*)g_WH)[i*2+0] = __halves2bfloat162(h[0], h[1]);
    ((__nv_bfloat162*)g_WH)[i*2+1] = __halves2bfloat162(h[2], h[3]);
    ((__nv_bfloat162*)g_WL)[i*2+0] = __halves2bfloat162(l[0], l[1]);
    ((__nv_bfloat162*)g_WL)[i*2+1] = __halves2bfloat162(l[2], l[3]);
}

// =================================================================================
// Kernel 4b: out = Yg @ W_out^T + b_out via nvcuda::wmma (bf16x3, fp32 acc).
// (unchanged from R8)
// =================================================================================
#define NCHUNK   32
#define TILE_B   10240
#define STAGE_B  (4*TILE_B)
#define BIAS_OFF (2*STAGE_B)
#define OG_SMEM  (BIAS_OFF + 16*128*4)

__global__ __launch_bounds__(256) void out_gemm_wmma(
    const float* __restrict__ b_out, float* __restrict__ out)
{
    extern __shared__ __align__(128) char smem[];
    const uint32_t sbase = smem_u32(smem);
    __nv_bfloat16* s_bf = (__nv_bfloat16*)smem;
    float* bias_s = (float*)(smem + BIAS_OFF);

    const int tid  = threadIdx.x;
    const int wid  = tid >> 5;
    const int warpM = wid & 3;
    const int warpN = wid >> 2;
    const int mb = blockIdx.x * 128;
    const int nb = blockIdx.y * 128;

    const __nv_bfloat16* __restrict__ srcs[4] = {g_YgH, g_YgL, g_WH, g_WL};

    auto issue_stage = [&](int chunk, int p) {
        const int kc = chunk * 32;
        const uint32_t sb = sbase + (uint32_t)p * STAGE_B;
#pragma unroll
        for (int s = 0; s < 8; ++s) {
            const int l = tid + s * 256;
            const int tile = l >> 9;
            const int w = l & 511;
            const int r = w >> 2;
            const int q = w & 3;
            const int grow = (tile < 2 ? mb : nb) + r;
            const __nv_bfloat16* g = srcs[tile] + (size_t)grow * DD + kc + q * 8;
            cp16(sb + tile * TILE_B + r * 80 + q * 16, g);
        }
        CP_COMMIT();
    };

    issue_stage(0, 0);

    for (int i = tid; i < 16*128; i += 256) bias_s[i] = b_out[nb + (i & 127)];
    __syncthreads();

    wmma::fragment<wmma::accumulator, 16, 16, 16, float> acc[2][4];
#pragma unroll
    for (int mt = 0; mt < 2; ++mt)
#pragma unroll
        for (int nt = 0; nt < 4; ++nt)
            wmma::load_matrix_sync(acc[mt][nt], &bias_s[warpN*64 + nt*16], 128,
                                   wmma::mem_row_major);

    for (int c = 0; c < NCHUNK; ++c) {
        const int p = c & 1;
        if (c + 1 < NCHUNK) { issue_stage(c + 1, p ^ 1); CP_WAIT(1); }
        else                { CP_WAIT(0); }
        __syncthreads();

        __nv_bfloat16* sAH = s_bf + (size_t)p * (STAGE_B/2);
        __nv_bfloat16* sAL = sAH + TILE_B/2;
        __nv_bfloat16* sBH = sAH + TILE_B;
        __nv_bfloat16* sBL = sAH + 3*(TILE_B/2);

#pragma unroll
        for (int ks = 0; ks < 2; ++ks) {
            wmma::fragment<wmma::matrix_a, 16, 16, 16, __nv_bfloat16, wmma::row_major> aH[2], aL[2];
#pragma unroll
            for (int mt = 0; mt < 2; ++mt) {
                wmma::load_matrix_sync(aH[mt], &sAH[(warpM*32 + mt*16)*40 + ks*16], 40);
                wmma::load_matrix_sync(aL[mt], &sAL[(warpM*32 + mt*16)*40 + ks*16], 40);
            }
#pragma unroll
            for (int nt = 0; nt < 4; ++nt) {
                wmma::fragment<wmma::matrix_b, 16, 16, 16, __nv_bfloat16, wmma::col_major> bH, bL;
                wmma::load_matrix_sync(bH, &sBH[(warpN*64 + nt*16)*40 + ks*16], 40);
                wmma::load_matrix_sync(bL, &sBL[(warpN*64 + nt*16)*40 + ks*16], 40);
#pragma unroll
                for (int mt = 0; mt < 2; ++mt) {
                    wmma::mma_sync(acc[mt][nt], aH[mt], bH, acc[mt][nt]);
                    wmma::mma_sync(acc[mt][nt], aH[mt], bL, acc[mt][nt]);
                    wmma::mma_sync(acc[mt][nt], aL[mt], bH, acc[mt][nt]);
                }
            }
        }
        __syncthreads();
    }

#pragma unroll
    for (int mt = 0; mt < 2; ++mt)
#pragma unroll
        for (int nt = 0; nt < 4; ++nt) {
            float* dst = out + (size_t)(mb + warpM*32 + mt*16) * DD + nb + warpN*64 + nt*16;
            wmma::store_matrix_sync(dst, acc[mt][nt], DD, wmma::mem_row_major);
        }
}

// =================================================================================
extern "C" void kernel_launch(void* const* d_in, const int* in_sizes, int n_in,
                              void* d_out, int out_size)
{
    const float* inp    = (const float*)d_in[0];
    const float* W_logA = (const float*)d_in[1];
    const float* b_logA = (const float*)d_in[2];
    const float* W_XBC  = (const float*)d_in[3];
    const float* b_XBC  = (const float*)d_in[4];
    const float* W_gate = (const float*)d_in[5];
    const float* b_gate = (const float*)d_in[6];
    const float* W_out  = (const float*)d_in[7];
    const float* b_out  = (const float*)d_in[8];
    float* out = (float*)d_out;

    proj_kernel<<<dim3(32, 5, 16), 128>>>(inp, W_logA, b_logA, W_XBC, b_XBC, W_gate, b_gate);
    scan_kernel<<<32, 256>>>();

    state_kernel<<<dim3(NCH-1, BHN), 256>>>();
    scan_state<<<dim3(BHN, 8), 256>>>();

    cudaFuncSetAttribute(attn_chunk, cudaFuncAttributeMaxDynamicSharedMemorySize, AC_SMEM);
    attn_chunk<<<dim3(NCH, BHN), 256, AC_SMEM>>>();

    cvt_kernel<<<1024, 256>>>(W_out);

    cudaFuncSetAttribute(out_gemm_wmma, cudaFuncAttributeMaxDynamicSharedMemorySize, OG_SMEM);
    out_gemm_wmma<<<dim3(16, 8), 256, OG_SMEM>>>(b_out, out);
}